// round 12
// baseline (speedup 1.0000x reference)
#include <cuda_runtime.h>
#include <cuda_fp16.h>
#include <math.h>

// ---------------- problem constants ----------------
#define NB   16
#define NC   128
#define NHC  512
#define HWSZ 4096

// ---------------- scratch ----------------
__device__ __half g_z[67108864];     // [E*B][C][HW] expert conv raw (fp16)
__device__ __half g_combp[8388608];  // [B][chunk8][px4096][16kp] fp16 (reused by norm2)
__device__ __half g_h1[33554432];
__device__ __half g_h2[8388608];     // COMPACT [B][HC][32][32] fp16
__device__ float  g_h3[2097152];
__device__ float  g_wts[128];
__device__ __half g_xr[8388608];     // [B][chunk8][h][w][16kp]
__device__ __half g_wr[1179648];     // [E][chunk8][tap9][oc128][16kp]
__device__ __half g_w1r[65536];      // [ht4][chunk8][hcl128][16kp]
__device__ __half g_w2r[65536];      // [chunk32][co128][16kp]
__device__ float g_part_exp[1024 * 64 * 2];
__device__ float g_ms_exp[1024 * 2];
__device__ float g_part1[128 * 32 * 2];
__device__ float g_ms1[128 * 2];
__device__ float g_part2[128 * 64 * 2];
__device__ float g_ms2[128 * 2];
__device__ float g_part3[128 * 16 * 2];
__device__ float g_ms3[128 * 2];

__device__ __forceinline__ float silu_f(float x) {
    return x / (1.0f + __expf(-x));
}
// permuted k index: j in [0,16) -> k, so thread r's 4 contiguous halves are
// k = {2r, 2r+1, 2r+8, 2r+9}
__device__ __forceinline__ int kmap(int j) {
    return ((j >> 2) * 2) + (j & 1) + ((j >> 1) & 1) * 8;
}
__device__ __forceinline__ void cp16(unsigned s, const void* g, int sz) {
    asm volatile("cp.async.cg.shared.global [%0], [%1], 16, %2;\n"
                 :: "r"(s), "l"(g), "r"(sz) : "memory");
}
__device__ __forceinline__ void cp_commit() {
    asm volatile("cp.async.commit_group;\n" ::: "memory");
}
__device__ __forceinline__ void cp_wait1() {
    asm volatile("cp.async.wait_group 1;\n" ::: "memory");
}
__device__ __forceinline__ void mma16(float* c, unsigned a0, unsigned a1, unsigned a2,
                                      unsigned a3, unsigned b0, unsigned b1) {
    asm volatile("mma.sync.aligned.m16n8k16.row.col.f32.f16.f16.f32 "
                 "{%0,%1,%2,%3}, {%4,%5,%6,%7}, {%8,%9}, {%0,%1,%2,%3};"
                 : "+f"(c[0]), "+f"(c[1]), "+f"(c[2]), "+f"(c[3])
                 : "r"(a0), "r"(a1), "r"(a2), "r"(a3), "r"(b0), "r"(b1));
}

// ---------------- transforms (fp16 + permute) ----------
__global__ void k_xform_x(const float* __restrict__ x) {
    int idx = blockIdx.x * 256 + threadIdx.x;   // 524288
    int w = idx & 63, h = (idx >> 6) & 63, chunk = (idx >> 12) & 7, b = idx >> 15;
    __align__(16) __half o[16];
#pragma unroll
    for (int j = 0; j < 16; j++) {
        int c = chunk * 16 + kmap(j);
        o[j] = __float2half(x[((b * 128 + c) << 12) + (h << 6) + w]);
    }
    uint4* dst = (uint4*)(g_xr + (size_t)idx * 16);
    dst[0] = ((uint4*)o)[0];
    dst[1] = ((uint4*)o)[1];
}

__global__ void k_xform_w(const float* __restrict__ w_exp) {
    int idx = blockIdx.x * 256 + threadIdx.x;   // 73728
    int oc = idx & 127;
    int t2 = idx >> 7;
    int tap = t2 % 9, ec = t2 / 9;
    int chunk = ec & 7, e = ec >> 3;
    __align__(16) __half o[16];
#pragma unroll
    for (int j = 0; j < 16; j++) {
        int c = chunk * 16 + kmap(j);
        o[j] = __float2half(w_exp[((e * 128 + oc) * 128 + c) * 9 + tap]);
    }
    uint4* dst = (uint4*)(g_wr + (size_t)idx * 16);
    dst[0] = ((uint4*)o)[0];
    dst[1] = ((uint4*)o)[1];
}

__global__ void k_xform_w1(const float* __restrict__ w_pw1) {
    int idx = blockIdx.x * 256 + threadIdx.x;   // 4096
    int hcl = idx & 127, chunk = (idx >> 7) & 7, ht = idx >> 10;
    __align__(16) __half o[16];
#pragma unroll
    for (int j = 0; j < 16; j++) {
        int c = chunk * 16 + kmap(j);
        o[j] = __float2half(w_pw1[(ht * 128 + hcl) * 128 + c]);
    }
    uint4* dst = (uint4*)(g_w1r + (size_t)idx * 16);
    dst[0] = ((uint4*)o)[0];
    dst[1] = ((uint4*)o)[1];
}

__global__ void k_xform_w2(const float* __restrict__ w_pw2) {
    int idx = blockIdx.x * 256 + threadIdx.x;   // 4096
    int co = idx & 127, chunk = idx >> 7;
    __align__(16) __half o[16];
#pragma unroll
    for (int j = 0; j < 16; j++) {
        int hc = chunk * 16 + kmap(j);
        o[j] = __float2half(w_pw2[co * NHC + hc]);
    }
    uint4* dst = (uint4*)(g_w2r + (size_t)idx * 16);
    dst[0] = ((uint4*)o)[0];
    dst[1] = ((uint4*)o)[1];
}

// ---------------- router ----------------
__global__ void k_router(const float* __restrict__ w1, const float* __restrict__ b1,
                         const float* __restrict__ w2, const float* __restrict__ b2) {
    __shared__ float feats[16 * 32];
    __shared__ float hid[16 * 64];
    __shared__ float lg[16 * 8];
    int tid = threadIdx.x;
    if (tid < 512) {
        int p = tid >> 5, f = tid & 31;
        int py = p >> 2, px = p & 3;
        int k = f & 7, kind = f >> 3;
        float freq = exp2f((float)k) * 3.14159265358979323846f;
        float cy = (py + 0.5f) * 0.25f;
        float cx = (px + 0.5f) * 0.25f;
        float v;
        if (kind == 0)      v = sinf(cy * freq);
        else if (kind == 1) v = cosf(cy * freq);
        else if (kind == 2) v = sinf(cx * freq);
        else                v = cosf(cx * freq);
        feats[p * 32 + f] = v;
    }
    __syncthreads();
    {
        int p = tid >> 6, hh = tid & 63;
        float a = b1[hh];
        for (int f = 0; f < 32; f++) a += feats[p * 32 + f] * w1[f * 64 + hh];
        hid[p * 64 + hh] = a / (1.0f + expf(-a));
    }
    __syncthreads();
    if (tid < 128) {
        int p = tid >> 3, e = tid & 7;
        float a = b2[e];
        for (int hh = 0; hh < 64; hh++) a += hid[p * 64 + hh] * w2[hh * 8 + e];
        lg[p * 8 + e] = a;
    }
    __syncthreads();
    if (tid < 16) {
        float mx = -1e30f;
        for (int e = 0; e < 8; e++) mx = fmaxf(mx, lg[tid * 8 + e]);
        float ex[8], s = 0.f;
        for (int e = 0; e < 8; e++) { ex[e] = expf(lg[tid * 8 + e] - mx); s += ex[e]; }
        float inv = 1.0f / s;
        for (int e = 0; e < 8; e++) g_wts[tid * 8 + e] = ex[e] * inv;
    }
}

// ---------------- expert conv: fp16 mma, block 64oc x 256px, 2 CTA/SM -------
#define XA0 0
#define XA1 3168
#define WA0 6336
#define WA1 10944
#define EXPF 15552

extern __shared__ float smem_all[];

__global__ __launch_bounds__(256, 2) void k_expert_mma() {
    int tid = threadIdx.x;
    int wid = tid >> 5, lane = tid & 31;
    int q = lane >> 2, r = lane & 3;
    int ocw = wid & 1, orow = wid >> 1;
    int hb = blockIdx.x, octile = blockIdx.y;
    int b = blockIdx.z & 15, e = blockIdx.z >> 4;
    unsigned smem_u = (unsigned)__cvta_generic_to_shared(smem_all);

    float acc[2][8][4];
#pragma unroll
    for (int i = 0; i < 2; i++)
#pragma unroll
        for (int j = 0; j < 8; j++)
#pragma unroll
            for (int l = 0; l < 4; l++) acc[i][j][l] = 0.f;

    if (tid < 192) {
        int bf = tid / 96, t = tid % 96;
        int row = t >> 4, side = (t >> 3) & 1, f = t & 7;
        smem_all[(bf ? XA1 : XA0) + row * 528 + (side ? 65 : 0) * 8 + f] = 0.f;
    }

    auto stage = [&](int chunk, int bf) {
        unsigned sx = smem_u + 4u * (bf ? XA1 : XA0);
        unsigned sw = smem_u + 4u * (bf ? WA1 : WA0);
        const __half* xs = g_xr + (size_t)(b * 8 + chunk) * 65536;
        for (int idx = tid; idx < 768; idx += 256) {
            int row = idx >> 7, f4 = idx & 127;
            int ih = 4 * hb - 1 + row;
            bool v = ((unsigned)ih < 64u);
            cp16(sx + (unsigned)(row * 2112 + 32 + f4 * 16),
                 xs + (size_t)(v ? ih : 0) * 1024 + f4 * 8, v ? 16 : 0);
        }
        const __half* ws = g_wr + (size_t)(e * 8 + chunk) * 18432 + octile * 1024;
        for (int idx = tid; idx < 1152; idx += 256) {
            int tap = idx >> 7, rem = idx & 127;
            cp16(sw + idx * 16u, ws + (size_t)tap * 2048 + rem * 8, 16);
        }
    };

    stage(0, 0); cp_commit();
    stage(1, 1); cp_commit();

    for (int c = 0; c < 8; c++) {
        cp_wait1();
        __syncthreads();
        int bf = c & 1;
        const char* sX = (const char*)smem_all + 4 * (bf ? XA1 : XA0);
        const char* sW = (const char*)smem_all + 4 * (bf ? WA1 : WA0);
#pragma unroll
        for (int tap = 0; tap < 9; tap++) {
            int dy = tap / 3, dx = tap - dy * 3;
            const char* wp = sW + tap * 2048 + (ocw * 32 + q) * 32 + r * 8;
            uint2 Alo[2], Ahi[2];
#pragma unroll
            for (int mt = 0; mt < 2; mt++) {
                Alo[mt] = *(const uint2*)(wp + mt * 512);
                Ahi[mt] = *(const uint2*)(wp + mt * 512 + 256);
            }
            const char* xp = sX + (orow + dy) * 2112 + (q + dx) * 32 + r * 8;
#pragma unroll
            for (int nt = 0; nt < 8; nt++) {
                uint2 Bv = *(const uint2*)(xp + nt * 256);
                mma16(acc[0][nt], Alo[0].x, Ahi[0].x, Alo[0].y, Ahi[0].y, Bv.x, Bv.y);
                mma16(acc[1][nt], Alo[1].x, Ahi[1].x, Alo[1].y, Ahi[1].y, Bv.x, Bv.y);
            }
        }
        __syncthreads();
        if (c + 2 < 8) stage(c + 2, bf);
        cp_commit();
    }

#pragma unroll
    for (int mt = 0; mt < 2; mt++) {
        float s1 = 0.f, s2 = 0.f;
#pragma unroll
        for (int nt = 0; nt < 8; nt++)
#pragma unroll
            for (int j = 0; j < 4; j++) {
                float v = acc[mt][nt][j];
                s1 += v; s2 += v * v;
            }
#pragma unroll
        for (int off = 16; off > 0; off >>= 1) {
            s1 += __shfl_xor_sync(0xffffffffu, s1, off);
            s2 += __shfl_xor_sync(0xffffffffu, s2, off);
        }
        if (lane == 0) {
            int g = octile * 4 + ocw * 2 + mt;
            int slot = (e * NB + b) * 8 + g;
            g_part_exp[(slot * 64 + hb * 4 + orow) * 2 + 0] = s1;
            g_part_exp[(slot * 64 + hb * 4 + orow) * 2 + 1] = s2;
        }
    }

    __half* stg = (__half*)smem_all;
#pragma unroll
    for (int mt = 0; mt < 2; mt++)
#pragma unroll
        for (int nt = 0; nt < 8; nt++) {
            int oc0 = ocw * 32 + mt * 16 + q;
            int px = orow * 64 + nt * 8 + 2 * r;
            *(__half2*)(stg + oc0 * 264 + px) =
                __floats2half2_rn(acc[mt][nt][0], acc[mt][nt][1]);
            *(__half2*)(stg + (oc0 + 8) * 264 + px) =
                __floats2half2_rn(acc[mt][nt][2], acc[mt][nt][3]);
        }
    __syncthreads();
    size_t zbase = (size_t)((e * NB + b) * NC + octile * 64) * HWSZ;
    for (int idx = tid; idx < 2048; idx += 256) {
        int oc = idx >> 5, p8 = (idx & 31) * 8;
        uint4 v = *(const uint4*)(stg + oc * 264 + p8);
        int h = 4 * hb + (p8 >> 6), w = p8 & 63;
        *(uint4*)(g_z + zbase + (size_t)oc * HWSZ + h * 64 + w) = v;
    }
}

// ---------------- finalize stats ----------------
__global__ void k_finalize(int which) {
    const float* part; float* ms; int nper, nslots; float invN;
    if (which == 0)      { part = g_part_exp; ms = g_ms_exp; nper = 64; nslots = 1024; invN = 1.0f / 65536.0f; }
    else if (which == 1) { part = g_part1;    ms = g_ms1;    nper = 32; nslots = 128;  invN = 1.0f / 262144.0f; }
    else if (which == 2) { part = g_part2;    ms = g_ms2;    nper = 64; nslots = 128;  invN = 1.0f / 262144.0f; }
    else                 { part = g_part3;    ms = g_ms3;    nper = 16; nslots = 128;  invN = 1.0f / 16384.0f; }
    int s = blockIdx.x * blockDim.x + threadIdx.x;
    if (s >= nslots) return;
    float s1 = 0.f, s2 = 0.f;
    for (int i = 0; i < nper; i++) {
        s1 += part[(s * nper + i) * 2 + 0];
        s2 += part[(s * nper + i) * 2 + 1];
    }
    float m = s1 * invN;
    float v = s2 * invN - m * m;
    ms[s * 2 + 0] = m;
    ms[s * 2 + 1] = rsqrtf(v + 1e-5f);
}

// ---------------- combine: 2 px per thread, half2 z loads ----------------
__global__ __launch_bounds__(256) void k_combine(const float* __restrict__ x,
                                                 const float* __restrict__ gs,
                                                 const float* __restrict__ gb) {
    int idx = blockIdx.x * 256 + threadIdx.x;   // 262144 = B*8*2048
    int px2 = idx & 2047, chunk = (idx >> 11) & 7, b = idx >> 14;
    int px = px2 * 2;
    int h = px >> 6, w = px & 63;
    int patch = ((h >> 4) << 2) + (w >> 4);   // same for px and px+1 (w even)
    float ra[16], rb[16];
#pragma unroll
    for (int j = 0; j < 16; j++) {
        int c = chunk * 16 + kmap(j);
        float2 xv = *(const float2*)(x + ((b * 128 + c) << 12) + px);
        ra[j] = xv.x; rb[j] = xv.y;
    }
#pragma unroll
    for (int e = 0; e < 8; e++) {
        float m  = g_ms_exp[(((e * NB + b) * 8) + chunk) * 2 + 0];
        float rs = g_ms_exp[(((e * NB + b) * 8) + chunk) * 2 + 1];
        float wt = g_wts[patch * 8 + e];
#pragma unroll
        for (int j = 0; j < 16; j++) {
            int c = chunk * 16 + kmap(j);
            __half2 zv = *(const __half2*)(g_z +
                ((size_t)((e * NB + b) * NC + c)) * HWSZ + px);
            float2 zf = __half22float2(zv);
            float gsc = gs[e * NC + c], gbc = gb[e * NC + c];
            ra[j] += wt * silu_f((zf.x - m) * rs * gsc + gbc);
            rb[j] += wt * silu_f((zf.y - m) * rs * gsc + gbc);
        }
    }
    __half2* dst = (__half2*)(g_combp + ((size_t)(b * 8 + chunk) * 4096 + px) * 16);
#pragma unroll
    for (int j = 0; j < 8; j++)
        dst[j] = __floats2half2_rn(ra[2 * j], ra[2 * j + 1]);
#pragma unroll
    for (int j = 0; j < 8; j++)
        dst[8 + j] = __floats2half2_rn(rb[2 * j], rb[2 * j + 1]);
}

// ---------------- pw1: fp16 mma, block 128hc x 128px ----------------
#define P1X0 0
#define P1W0 1024
#define P1X1 2048
#define P1W1 3072
#define RED1 16896
#define PW1F 16928

__global__ __launch_bounds__(256, 2) void k_pw1_mma() {
    int tid = threadIdx.x;
    int wid = tid >> 5, lane = tid & 31;
    int q = lane >> 2, r = lane & 3;
    int ocw = wid >> 1, ph = wid & 1;
    int ht = blockIdx.x, pt = blockIdx.y, b = blockIdx.z;
    unsigned smem_u = (unsigned)__cvta_generic_to_shared(smem_all);

    float acc[2][8][4];
#pragma unroll
    for (int i = 0; i < 2; i++)
#pragma unroll
        for (int j = 0; j < 8; j++)
#pragma unroll
            for (int l = 0; l < 4; l++) acc[i][j][l] = 0.f;

    auto stage = [&](int chunk, int bf) {
        unsigned sxa = smem_u + 4u * (bf ? P1X1 : P1X0);
        unsigned swa = smem_u + 4u * (bf ? P1W1 : P1W0);
        const __half* xsrc = g_combp + ((size_t)(b * 8 + chunk) * 4096 + pt * 128) * 16;
        const __half* wsrc = g_w1r + (ht * 8 + chunk) * 2048;
        cp16(sxa + tid * 16u, xsrc + tid * 8, 16);
        cp16(swa + tid * 16u, wsrc + tid * 8, 16);
    };

    stage(0, 0); cp_commit();
    stage(1, 1); cp_commit();

    for (int k = 0; k < 8; k++) {
        cp_wait1();
        __syncthreads();
        int bf = k & 1;
        const char* sX = (const char*)smem_all + 4 * (bf ? P1X1 : P1X0);
        const char* sW = (const char*)smem_all + 4 * (bf ? P1W1 : P1W0);
        const char* wp = sW + (ocw * 32 + q) * 32 + r * 8;
        uint2 Alo[2], Ahi[2];
#pragma unroll
        for (int mt = 0; mt < 2; mt++) {
            Alo[mt] = *(const uint2*)(wp + mt * 512);
            Ahi[mt] = *(const uint2*)(wp + mt * 512 + 256);
        }
#pragma unroll
        for (int nt = 0; nt < 8; nt++) {
            const char* xp = sX + (ph * 64 + nt * 8 + q) * 32 + r * 8;
            uint2 Bv = *(const uint2*)(xp);
            mma16(acc[0][nt], Alo[0].x, Ahi[0].x, Alo[0].y, Ahi[0].y, Bv.x, Bv.y);
            mma16(acc[1][nt], Alo[1].x, Ahi[1].x, Alo[1].y, Ahi[1].y, Bv.x, Bv.y);
        }
        __syncthreads();
        if (k + 2 < 8) stage(k + 2, bf);
        cp_commit();
    }

    float s1 = 0.f, s2 = 0.f;
#pragma unroll
    for (int i = 0; i < 2; i++)
#pragma unroll
        for (int j = 0; j < 8; j++)
#pragma unroll
            for (int l = 0; l < 4; l++) {
                float v = acc[i][j][l];
                s1 += v; s2 += v * v;
            }
#pragma unroll
    for (int off = 16; off > 0; off >>= 1) {
        s1 += __shfl_xor_sync(0xffffffffu, s1, off);
        s2 += __shfl_xor_sync(0xffffffffu, s2, off);
    }
    float* red = smem_all + RED1;
    if (lane == 0) { red[wid * 2] = s1; red[wid * 2 + 1] = s2; }

    float* stg = smem_all;
#pragma unroll
    for (int mt = 0; mt < 2; mt++)
#pragma unroll
        for (int nt = 0; nt < 8; nt++)
#pragma unroll
            for (int j = 0; j < 4; j++) {
                int hcl = ocw * 32 + mt * 16 + q + 8 * (j >> 1);
                int w = nt * 8 + 2 * r + (j & 1);
                stg[hcl * 132 + ph * 64 + w] = acc[mt][nt][j];
            }
    __syncthreads();
    if (tid < 2) {
        float a = red[tid * 8 + 0] + red[tid * 8 + 2] + red[tid * 8 + 4] + red[tid * 8 + 6];
        float bq = red[tid * 8 + 1] + red[tid * 8 + 3] + red[tid * 8 + 5] + red[tid * 8 + 7];
        int slot = b * 8 + ht * 2 + tid;
        g_part1[(slot * 32 + pt) * 2 + 0] = a;
        g_part1[(slot * 32 + pt) * 2 + 1] = bq;
    }
    for (int idx = tid; idx < 4096; idx += 256) {
        int hcl = idx >> 5, p4 = (idx & 31) * 4;
        float4 v = *(const float4*)(stg + hcl * 132 + p4);
        __half2* dst = (__half2*)(g_h1 + (size_t)(b * NHC + ht * 128 + hcl) * HWSZ +
                                  pt * 128 + p4);
        dst[0] = __floats2half2_rn(v.x, v.y);
        dst[1] = __floats2half2_rn(v.z, v.w);
    }
}

// ---------------- dw: compact stride-2 output, fp16 ----------------
__global__ __launch_bounds__(256) void k_dw(const float* __restrict__ w_dw,
                                            const float* __restrict__ s1v,
                                            const float* __restrict__ b1v) {
    __shared__ float sa[4356];
    __shared__ float red[512];
    int tid = threadIdx.x;
    int ch = blockIdx.x, b = blockIdx.y;
    float m  = g_ms1[(b * 8 + (ch >> 6)) * 2 + 0];
    float rs = g_ms1[(b * 8 + (ch >> 6)) * 2 + 1];
    float sc = s1v[ch], bi = b1v[ch];
    for (int idx = tid; idx < 4356; idx += 256) sa[idx] = 0.f;
    __syncthreads();
    const __half* src = g_h1 + (size_t)(b * NHC + ch) * 4096;
    for (int idx = tid; idx < 512; idx += 256) {
        int r = idx >> 3, w8 = (idx & 7) * 8;
        __align__(16) __half raw[8];
        *(uint4*)raw = *(const uint4*)(src + r * 64 + w8);
        float* d = sa + (r + 1) * 66 + 1 + w8;
#pragma unroll
        for (int j = 0; j < 8; j++)
            d[j] = silu_f((__half2float(raw[j]) - m) * rs * sc + bi);
    }
    __syncthreads();
    float wd[9];
#pragma unroll
    for (int j = 0; j < 9; j++) wd[j] = w_dw[ch * 9 + j];
    int r = tid >> 2, w0 = (tid & 3) * 16;
    float s1 = 0.f, s2 = 0.f;
    __half* orow = g_h2 + (size_t)(b * NHC + ch) * 1024 + (r >> 1) * 32;
    bool reven = (r & 1) == 0;
#pragma unroll
    for (int k = 0; k < 16; k++) {
        int w = w0 + k;
        float a = 0.f;
#pragma unroll
        for (int dr = 0; dr < 3; dr++)
#pragma unroll
            for (int dt = 0; dt < 3; dt++)
                a += sa[(r + dr) * 66 + w + dt] * wd[dr * 3 + dt];
        s1 += a; s2 += a * a;
        if (reven && !(w & 1)) orow[w >> 1] = __float2half(a);
    }
    red[tid] = s1; red[256 + tid] = s2;
    __syncthreads();
    for (int st = 128; st > 0; st >>= 1) {
        if (tid < st) { red[tid] += red[tid + st]; red[256 + tid] += red[256 + tid + st]; }
        __syncthreads();
    }
    if (tid == 0) {
        int slot = b * 8 + (ch >> 6);
        g_part2[(slot * 64 + (ch & 63)) * 2 + 0] = red[0];
        g_part2[(slot * 64 + (ch & 63)) * 2 + 1] = red[256];
    }
}

// ---------------- norm2: GN2+SiLU -> pw2 B operand (reuses g_combp) --------
__global__ void k_norm2(const float* __restrict__ s2v, const float* __restrict__ b2v) {
    int idx = blockIdx.x * 256 + threadIdx.x;   // 524288 = B*32*1024
    int px = idx & 1023, chunk = (idx >> 10) & 31, b = idx >> 15;
    __align__(16) __half o[16];
#pragma unroll
    for (int j = 0; j < 16; j++) {
        int hc = chunk * 16 + kmap(j);
        float v = __half2float(g_h2[(size_t)(b * NHC + hc) * 1024 + px]);
        float m  = g_ms2[(b * 8 + (hc >> 6)) * 2 + 0];
        float rr = g_ms2[(b * 8 + (hc >> 6)) * 2 + 1];
        o[j] = __float2half(silu_f((v - m) * rr * s2v[hc] + b2v[hc]));
    }
    uint4* dst = (uint4*)(g_combp + (size_t)idx * 16);
    dst[0] = ((uint4*)o)[0];
    dst[1] = ((uint4*)o)[1];
}

// ---------------- pw2: fp16 mma, block 128co x 64px, K=512 -----------------
__global__ __launch_bounds__(256) void k_pw2_mma() {
    __shared__ __align__(16) float sm[3072];
    int tid = threadIdx.x;
    int wid = tid >> 5, lane = tid & 31;
    int q = lane >> 2, r = lane & 3;
    int pt = blockIdx.x, b = blockIdx.y;
    unsigned smem_u = (unsigned)__cvta_generic_to_shared(sm);

    float acc[8][4];
#pragma unroll
    for (int j = 0; j < 8; j++)
#pragma unroll
        for (int l = 0; l < 4; l++) acc[j][l] = 0.f;

    auto stage = [&](int chunk, int bf) {
        unsigned sx = smem_u + 4u * (bf ? 1536 : 0);
        unsigned sw = smem_u + 4u * (bf ? 2048 : 512);
        const __half* xsrc = g_combp + ((size_t)(b * 32 + chunk) * 1024 + pt * 64) * 16;
        const __half* wsrc = g_w2r + (size_t)chunk * 2048;
        if (tid < 128) cp16(sx + tid * 16u, xsrc + tid * 8, 16);
        cp16(sw + tid * 16u, wsrc + tid * 8, 16);
    };

    stage(0, 0); cp_commit();
    stage(1, 1); cp_commit();

    for (int k = 0; k < 32; k++) {
        cp_wait1();
        __syncthreads();
        int bf = k & 1;
        const char* sX = (const char*)sm + 4 * (bf ? 1536 : 0);
        const char* sW = (const char*)sm + 4 * (bf ? 2048 : 512);
        const char* wp = sW + (wid * 16 + q) * 32 + r * 8;
        uint2 Alo = *(const uint2*)(wp);
        uint2 Ahi = *(const uint2*)(wp + 256);
#pragma unroll
        for (int nt = 0; nt < 8; nt++) {
            const char* xp = sX + (nt * 8 + q) * 32 + r * 8;
            uint2 Bv = *(const uint2*)(xp);
            mma16(acc[nt], Alo.x, Ahi.x, Alo.y, Ahi.y, Bv.x, Bv.y);
        }
        __syncthreads();
        if (k + 2 < 32) stage(k + 2, bf);
        cp_commit();
    }

    float s1 = 0.f, s2 = 0.f;
#pragma unroll
    for (int j = 0; j < 8; j++)
#pragma unroll
        for (int l = 0; l < 4; l++) {
            float v = acc[j][l];
            s1 += v; s2 += v * v;
        }
#pragma unroll
    for (int off = 16; off > 0; off >>= 1) {
        s1 += __shfl_xor_sync(0xffffffffu, s1, off);
        s2 += __shfl_xor_sync(0xffffffffu, s2, off);
    }
    if (lane == 0) {
        g_part3[((b * 8 + wid) * 16 + pt) * 2 + 0] = s1;
        g_part3[((b * 8 + wid) * 16 + pt) * 2 + 1] = s2;
    }

#pragma unroll
    for (int nt = 0; nt < 8; nt++)
#pragma unroll
        for (int l = 0; l < 4; l++) {
            int co = wid * 16 + q + 8 * (l >> 1);
            int pi = pt * 64 + nt * 8 + 2 * r + (l & 1);
            g_h3[((b * NC + co) << 10) + pi] = acc[nt][l];
        }
}

// ---------------- final ----------------
__global__ void k_out(float* __restrict__ out,
                      const float* __restrict__ s3v, const float* __restrict__ b3v) {
    int idx = blockIdx.x * 256 + threadIdx.x;
    int co = (idx >> 10) & 127, b = idx >> 17;
    int g = co >> 4;
    float m  = g_ms3[(b * 8 + g) * 2 + 0];
    float rs = g_ms3[(b * 8 + g) * 2 + 1];
    float t = (g_h3[idx] - m) * rs * s3v[co] + b3v[co];
    out[idx] = silu_f(t);
}

// ---------------- launch ----------------
extern "C" void kernel_launch(void* const* d_in, const int* in_sizes, int n_in,
                              void* d_out, int out_size) {
    const float* x      = (const float*)d_in[0];
    const float* w_exp  = (const float*)d_in[1];
    const float* gs_e   = (const float*)d_in[2];
    const float* gb_e   = (const float*)d_in[3];
    const float* w1     = (const float*)d_in[4];
    const float* b1     = (const float*)d_in[5];
    const float* w2     = (const float*)d_in[6];
    const float* b2     = (const float*)d_in[7];
    const float* w_pw1  = (const float*)d_in[8];
    const float* gn1_s  = (const float*)d_in[9];
    const float* gn1_b  = (const float*)d_in[10];
    const float* w_dw   = (const float*)d_in[11];
    const float* gn2_s  = (const float*)d_in[12];
    const float* gn2_b  = (const float*)d_in[13];
    const float* w_pw2  = (const float*)d_in[14];
    const float* gn3_s  = (const float*)d_in[15];
    const float* gn3_b  = (const float*)d_in[16];
    float* out = (float*)d_out;

    static bool attr_done = false;
    if (!attr_done) {
        cudaFuncSetAttribute(k_expert_mma, cudaFuncAttributeMaxDynamicSharedMemorySize,
                             EXPF * 4);
        cudaFuncSetAttribute(k_pw1_mma, cudaFuncAttributeMaxDynamicSharedMemorySize,
                             PW1F * 4);
        attr_done = true;
    }

    // expert at launch index 3 so ncu's fixed sample lands on it
    k_xform_x<<<2048, 256>>>(x);
    k_xform_w<<<288, 256>>>(w_exp);
    k_router<<<1, 1024>>>(w1, b1, w2, b2);
    k_expert_mma<<<dim3(16, 2, 128), 256, EXPF * 4>>>();
    k_xform_w1<<<16, 256>>>(w_pw1);
    k_xform_w2<<<16, 256>>>(w_pw2);
    k_finalize<<<4, 256>>>(0);
    k_combine<<<1024, 256>>>(x, gs_e, gb_e);
    k_pw1_mma<<<dim3(4, 32, 16), 256, PW1F * 4>>>();
    k_finalize<<<4, 256>>>(1);
    k_dw<<<dim3(512, 16), 256>>>(w_dw, gn1_s, gn1_b);
    k_finalize<<<4, 256>>>(2);
    k_norm2<<<2048, 256>>>(gn2_s, gn2_b);
    k_pw2_mma<<<dim3(16, 16), 256>>>();
    k_finalize<<<4, 256>>>(3);
    k_out<<<8192, 256>>>(out, gn3_s, gn3_b);
}

// round 14
// speedup vs baseline: 1.4744x; 1.4744x over previous
#include <cuda_runtime.h>
#include <cuda_fp16.h>
#include <math.h>

// ---------------- problem constants ----------------
#define NB   16
#define NC   128
#define NHC  512
#define HWSZ 4096

// ---------------- scratch ----------------
__device__ __half g_z[67108864];     // [E*B][C][HW] expert conv raw (fp16)
__device__ __half g_combp[8388608];  // [B][chunk8][px4096][16kp] fp16 (reused by norm2)
__device__ __half g_h1[33554432];
__device__ __half g_h2[8388608];     // COMPACT [B][HC][32][32] fp16
__device__ float  g_h3[2097152];
__device__ float  g_wts[128];
__device__ __half g_xr[8388608];     // [B][chunk8][h][w][16kp]
__device__ __half g_wr[1179648];     // [E][chunk8][tap9][oc128][16kp]
__device__ __half g_w1r[65536];      // [ht4][chunk8][hcl128][16kp]
__device__ __half g_w2r[65536];      // [chunk32][co128][16kp]
__device__ float g_part_exp[1024 * 64 * 2];
__device__ float g_ms_exp[1024 * 2];
__device__ float g_part1[128 * 32 * 2];
__device__ float g_ms1[128 * 2];
__device__ float g_part2[128 * 64 * 2];
__device__ float g_ms2[128 * 2];
__device__ float g_part3[128 * 16 * 2];
__device__ float g_ms3[128 * 2];

__device__ __forceinline__ float silu_f(float x) {
    return x / (1.0f + __expf(-x));
}
// permuted k index: j in [0,16) -> k, so thread r's 4 contiguous halves are
// k = {2r, 2r+1, 2r+8, 2r+9}
__device__ __forceinline__ int kmap(int j) {
    return ((j >> 2) * 2) + (j & 1) + ((j >> 1) & 1) * 8;
}
__device__ __forceinline__ void cp16(unsigned s, const void* g, int sz) {
    asm volatile("cp.async.cg.shared.global [%0], [%1], 16, %2;\n"
                 :: "r"(s), "l"(g), "r"(sz) : "memory");
}
__device__ __forceinline__ void cp_commit() {
    asm volatile("cp.async.commit_group;\n" ::: "memory");
}
__device__ __forceinline__ void cp_wait1() {
    asm volatile("cp.async.wait_group 1;\n" ::: "memory");
}
__device__ __forceinline__ void mma16(float* c, unsigned a0, unsigned a1, unsigned a2,
                                      unsigned a3, unsigned b0, unsigned b1) {
    asm volatile("mma.sync.aligned.m16n8k16.row.col.f32.f16.f16.f32 "
                 "{%0,%1,%2,%3}, {%4,%5,%6,%7}, {%8,%9}, {%0,%1,%2,%3};"
                 : "+f"(c[0]), "+f"(c[1]), "+f"(c[2]), "+f"(c[3])
                 : "r"(a0), "r"(a1), "r"(a2), "r"(a3), "r"(b0), "r"(b1));
}

// ---------------- transforms (fp16 + permute) ----------
__global__ void k_xform_x(const float* __restrict__ x) {
    int idx = blockIdx.x * 256 + threadIdx.x;   // 524288
    int w = idx & 63, h = (idx >> 6) & 63, chunk = (idx >> 12) & 7, b = idx >> 15;
    __align__(16) __half o[16];
#pragma unroll
    for (int j = 0; j < 16; j++) {
        int c = chunk * 16 + kmap(j);
        o[j] = __float2half(x[((b * 128 + c) << 12) + (h << 6) + w]);
    }
    uint4* dst = (uint4*)(g_xr + (size_t)idx * 16);
    dst[0] = ((uint4*)o)[0];
    dst[1] = ((uint4*)o)[1];
}

__global__ void k_xform_w(const float* __restrict__ w_exp) {
    int idx = blockIdx.x * 256 + threadIdx.x;   // 73728
    int oc = idx & 127;
    int t2 = idx >> 7;
    int tap = t2 % 9, ec = t2 / 9;
    int chunk = ec & 7, e = ec >> 3;
    __align__(16) __half o[16];
#pragma unroll
    for (int j = 0; j < 16; j++) {
        int c = chunk * 16 + kmap(j);
        o[j] = __float2half(w_exp[((e * 128 + oc) * 128 + c) * 9 + tap]);
    }
    uint4* dst = (uint4*)(g_wr + (size_t)idx * 16);
    dst[0] = ((uint4*)o)[0];
    dst[1] = ((uint4*)o)[1];
}

__global__ void k_xform_w1(const float* __restrict__ w_pw1) {
    int idx = blockIdx.x * 256 + threadIdx.x;   // 4096
    int hcl = idx & 127, chunk = (idx >> 7) & 7, ht = idx >> 10;
    __align__(16) __half o[16];
#pragma unroll
    for (int j = 0; j < 16; j++) {
        int c = chunk * 16 + kmap(j);
        o[j] = __float2half(w_pw1[(ht * 128 + hcl) * 128 + c]);
    }
    uint4* dst = (uint4*)(g_w1r + (size_t)idx * 16);
    dst[0] = ((uint4*)o)[0];
    dst[1] = ((uint4*)o)[1];
}

__global__ void k_xform_w2(const float* __restrict__ w_pw2) {
    int idx = blockIdx.x * 256 + threadIdx.x;   // 4096
    int co = idx & 127, chunk = idx >> 7;
    __align__(16) __half o[16];
#pragma unroll
    for (int j = 0; j < 16; j++) {
        int hc = chunk * 16 + kmap(j);
        o[j] = __float2half(w_pw2[co * NHC + hc]);
    }
    uint4* dst = (uint4*)(g_w2r + (size_t)idx * 16);
    dst[0] = ((uint4*)o)[0];
    dst[1] = ((uint4*)o)[1];
}

// ---------------- router ----------------
__global__ void k_router(const float* __restrict__ w1, const float* __restrict__ b1,
                         const float* __restrict__ w2, const float* __restrict__ b2) {
    __shared__ float feats[16 * 32];
    __shared__ float hid[16 * 64];
    __shared__ float lg[16 * 8];
    int tid = threadIdx.x;
    if (tid < 512) {
        int p = tid >> 5, f = tid & 31;
        int py = p >> 2, px = p & 3;
        int k = f & 7, kind = f >> 3;
        float freq = exp2f((float)k) * 3.14159265358979323846f;
        float cy = (py + 0.5f) * 0.25f;
        float cx = (px + 0.5f) * 0.25f;
        float v;
        if (kind == 0)      v = sinf(cy * freq);
        else if (kind == 1) v = cosf(cy * freq);
        else if (kind == 2) v = sinf(cx * freq);
        else                v = cosf(cx * freq);
        feats[p * 32 + f] = v;
    }
    __syncthreads();
    {
        int p = tid >> 6, hh = tid & 63;
        float a = b1[hh];
        for (int f = 0; f < 32; f++) a += feats[p * 32 + f] * w1[f * 64 + hh];
        hid[p * 64 + hh] = a / (1.0f + expf(-a));
    }
    __syncthreads();
    if (tid < 128) {
        int p = tid >> 3, e = tid & 7;
        float a = b2[e];
        for (int hh = 0; hh < 64; hh++) a += hid[p * 64 + hh] * w2[hh * 8 + e];
        lg[p * 8 + e] = a;
    }
    __syncthreads();
    if (tid < 16) {
        float mx = -1e30f;
        for (int e = 0; e < 8; e++) mx = fmaxf(mx, lg[tid * 8 + e]);
        float ex[8], s = 0.f;
        for (int e = 0; e < 8; e++) { ex[e] = expf(lg[tid * 8 + e] - mx); s += ex[e]; }
        float inv = 1.0f / s;
        for (int e = 0; e < 8; e++) g_wts[tid * 8 + e] = ex[e] * inv;
    }
}

// ---------------- expert conv: fp16 mma, block 64oc x 256px, 2 CTA/SM -------
#define XA0 0
#define XA1 3168
#define WA0 6336
#define WA1 10944
#define EXPF 15552

extern __shared__ float smem_all[];

__global__ __launch_bounds__(256, 2) void k_expert_mma() {
    int tid = threadIdx.x;
    int wid = tid >> 5, lane = tid & 31;
    int q = lane >> 2, r = lane & 3;
    int ocw = wid & 1, orow = wid >> 1;
    int hb = blockIdx.x, octile = blockIdx.y;
    int b = blockIdx.z & 15, e = blockIdx.z >> 4;
    unsigned smem_u = (unsigned)__cvta_generic_to_shared(smem_all);

    float acc[2][8][4];
#pragma unroll
    for (int i = 0; i < 2; i++)
#pragma unroll
        for (int j = 0; j < 8; j++)
#pragma unroll
            for (int l = 0; l < 4; l++) acc[i][j][l] = 0.f;

    if (tid < 192) {
        int bf = tid / 96, t = tid % 96;
        int row = t >> 4, side = (t >> 3) & 1, f = t & 7;
        smem_all[(bf ? XA1 : XA0) + row * 528 + (side ? 65 : 0) * 8 + f] = 0.f;
    }

    auto stage = [&](int chunk, int bf) {
        unsigned sx = smem_u + 4u * (bf ? XA1 : XA0);
        unsigned sw = smem_u + 4u * (bf ? WA1 : WA0);
        const __half* xs = g_xr + (size_t)(b * 8 + chunk) * 65536;
        for (int idx = tid; idx < 768; idx += 256) {
            int row = idx >> 7, f4 = idx & 127;
            int ih = 4 * hb - 1 + row;
            bool v = ((unsigned)ih < 64u);
            cp16(sx + (unsigned)(row * 2112 + 32 + f4 * 16),
                 xs + (size_t)(v ? ih : 0) * 1024 + f4 * 8, v ? 16 : 0);
        }
        const __half* ws = g_wr + (size_t)(e * 8 + chunk) * 18432 + octile * 1024;
        for (int idx = tid; idx < 1152; idx += 256) {
            int tap = idx >> 7, rem = idx & 127;
            cp16(sw + idx * 16u, ws + (size_t)tap * 2048 + rem * 8, 16);
        }
    };

    stage(0, 0); cp_commit();
    stage(1, 1); cp_commit();

    for (int c = 0; c < 8; c++) {
        cp_wait1();
        __syncthreads();
        int bf = c & 1;
        const char* sX = (const char*)smem_all + 4 * (bf ? XA1 : XA0);
        const char* sW = (const char*)smem_all + 4 * (bf ? WA1 : WA0);
#pragma unroll
        for (int tap = 0; tap < 9; tap++) {
            int dy = tap / 3, dx = tap - dy * 3;
            const char* wp = sW + tap * 2048 + (ocw * 32 + q) * 32 + r * 8;
            uint2 Alo[2], Ahi[2];
#pragma unroll
            for (int mt = 0; mt < 2; mt++) {
                Alo[mt] = *(const uint2*)(wp + mt * 512);
                Ahi[mt] = *(const uint2*)(wp + mt * 512 + 256);
            }
            const char* xp = sX + (orow + dy) * 2112 + (q + dx) * 32 + r * 8;
#pragma unroll
            for (int nt = 0; nt < 8; nt++) {
                uint2 Bv = *(const uint2*)(xp + nt * 256);
                mma16(acc[0][nt], Alo[0].x, Ahi[0].x, Alo[0].y, Ahi[0].y, Bv.x, Bv.y);
                mma16(acc[1][nt], Alo[1].x, Ahi[1].x, Alo[1].y, Ahi[1].y, Bv.x, Bv.y);
            }
        }
        __syncthreads();
        if (c + 2 < 8) stage(c + 2, bf);
        cp_commit();
    }

#pragma unroll
    for (int mt = 0; mt < 2; mt++) {
        float s1 = 0.f, s2 = 0.f;
#pragma unroll
        for (int nt = 0; nt < 8; nt++)
#pragma unroll
            for (int j = 0; j < 4; j++) {
                float v = acc[mt][nt][j];
                s1 += v; s2 += v * v;
            }
#pragma unroll
        for (int off = 16; off > 0; off >>= 1) {
            s1 += __shfl_xor_sync(0xffffffffu, s1, off);
            s2 += __shfl_xor_sync(0xffffffffu, s2, off);
        }
        if (lane == 0) {
            int g = octile * 4 + ocw * 2 + mt;
            int slot = (e * NB + b) * 8 + g;
            g_part_exp[(slot * 64 + hb * 4 + orow) * 2 + 0] = s1;
            g_part_exp[(slot * 64 + hb * 4 + orow) * 2 + 1] = s2;
        }
    }

    __half* stg = (__half*)smem_all;
#pragma unroll
    for (int mt = 0; mt < 2; mt++)
#pragma unroll
        for (int nt = 0; nt < 8; nt++) {
            int oc0 = ocw * 32 + mt * 16 + q;
            int px = orow * 64 + nt * 8 + 2 * r;
            *(__half2*)(stg + oc0 * 264 + px) =
                __floats2half2_rn(acc[mt][nt][0], acc[mt][nt][1]);
            *(__half2*)(stg + (oc0 + 8) * 264 + px) =
                __floats2half2_rn(acc[mt][nt][2], acc[mt][nt][3]);
        }
    __syncthreads();
    size_t zbase = (size_t)((e * NB + b) * NC + octile * 64) * HWSZ;
    for (int idx = tid; idx < 2048; idx += 256) {
        int oc = idx >> 5, p8 = (idx & 31) * 8;
        uint4 v = *(const uint4*)(stg + oc * 264 + p8);
        int h = 4 * hb + (p8 >> 6), w = p8 & 63;
        *(uint4*)(g_z + zbase + (size_t)oc * HWSZ + h * 64 + w) = v;
    }
}

// ---------------- finalize stats ----------------
__global__ void k_finalize(int which) {
    const float* part; float* ms; int nper, nslots; float invN;
    if (which == 0)      { part = g_part_exp; ms = g_ms_exp; nper = 64; nslots = 1024; invN = 1.0f / 65536.0f; }
    else if (which == 1) { part = g_part1;    ms = g_ms1;    nper = 32; nslots = 128;  invN = 1.0f / 262144.0f; }
    else if (which == 2) { part = g_part2;    ms = g_ms2;    nper = 64; nslots = 128;  invN = 1.0f / 262144.0f; }
    else                 { part = g_part3;    ms = g_ms3;    nper = 16; nslots = 128;  invN = 1.0f / 16384.0f; }
    int s = blockIdx.x * blockDim.x + threadIdx.x;
    if (s >= nslots) return;
    float s1 = 0.f, s2 = 0.f;
    for (int i = 0; i < nper; i++) {
        s1 += part[(s * nper + i) * 2 + 0];
        s2 += part[(s * nper + i) * 2 + 1];
    }
    float m = s1 * invN;
    float v = s2 * invN - m * m;
    ms[s * 2 + 0] = m;
    ms[s * 2 + 1] = rsqrtf(v + 1e-5f);
}

// ---------------- combine: 2 px per thread, half2 z loads ----------------
__global__ __launch_bounds__(256) void k_combine(const float* __restrict__ x,
                                                 const float* __restrict__ gs,
                                                 const float* __restrict__ gb) {
    int idx = blockIdx.x * 256 + threadIdx.x;   // 262144 = B*8*2048
    int px2 = idx & 2047, chunk = (idx >> 11) & 7, b = idx >> 14;
    int px = px2 * 2;
    int h = px >> 6, w = px & 63;
    int patch = ((h >> 4) << 2) + (w >> 4);   // same for px and px+1 (w even)
    float ra[16], rb[16];
#pragma unroll
    for (int j = 0; j < 16; j++) {
        int c = chunk * 16 + kmap(j);
        float2 xv = *(const float2*)(x + ((b * 128 + c) << 12) + px);
        ra[j] = xv.x; rb[j] = xv.y;
    }
#pragma unroll
    for (int e = 0; e < 8; e++) {
        float m  = g_ms_exp[(((e * NB + b) * 8) + chunk) * 2 + 0];
        float rs = g_ms_exp[(((e * NB + b) * 8) + chunk) * 2 + 1];
        float wt = g_wts[patch * 8 + e];
#pragma unroll
        for (int j = 0; j < 16; j++) {
            int c = chunk * 16 + kmap(j);
            __half2 zv = *(const __half2*)(g_z +
                ((size_t)((e * NB + b) * NC + c)) * HWSZ + px);
            float2 zf = __half22float2(zv);
            float gsc = gs[e * NC + c], gbc = gb[e * NC + c];
            ra[j] += wt * silu_f((zf.x - m) * rs * gsc + gbc);
            rb[j] += wt * silu_f((zf.y - m) * rs * gsc + gbc);
        }
    }
    __half2* dst = (__half2*)(g_combp + ((size_t)(b * 8 + chunk) * 4096 + px) * 16);
#pragma unroll
    for (int j = 0; j < 8; j++)
        dst[j] = __floats2half2_rn(ra[2 * j], ra[2 * j + 1]);
#pragma unroll
    for (int j = 0; j < 8; j++)
        dst[8 + j] = __floats2half2_rn(rb[2 * j], rb[2 * j + 1]);
}

// ---------------- pw1: fp16 mma, block 128hc x 128px ----------------
#define P1X0 0
#define P1W0 1024
#define P1X1 2048
#define P1W1 3072
#define RED1 16896
#define PW1F 16928

__global__ __launch_bounds__(256, 2) void k_pw1_mma() {
    int tid = threadIdx.x;
    int wid = tid >> 5, lane = tid & 31;
    int q = lane >> 2, r = lane & 3;
    int ocw = wid >> 1, ph = wid & 1;
    int ht = blockIdx.x, pt = blockIdx.y, b = blockIdx.z;
    unsigned smem_u = (unsigned)__cvta_generic_to_shared(smem_all);

    float acc[2][8][4];
#pragma unroll
    for (int i = 0; i < 2; i++)
#pragma unroll
        for (int j = 0; j < 8; j++)
#pragma unroll
            for (int l = 0; l < 4; l++) acc[i][j][l] = 0.f;

    auto stage = [&](int chunk, int bf) {
        unsigned sxa = smem_u + 4u * (bf ? P1X1 : P1X0);
        unsigned swa = smem_u + 4u * (bf ? P1W1 : P1W0);
        const __half* xsrc = g_combp + ((size_t)(b * 8 + chunk) * 4096 + pt * 128) * 16;
        const __half* wsrc = g_w1r + (ht * 8 + chunk) * 2048;
        cp16(sxa + tid * 16u, xsrc + tid * 8, 16);
        cp16(swa + tid * 16u, wsrc + tid * 8, 16);
    };

    stage(0, 0); cp_commit();
    stage(1, 1); cp_commit();

    for (int k = 0; k < 8; k++) {
        cp_wait1();
        __syncthreads();
        int bf = k & 1;
        const char* sX = (const char*)smem_all + 4 * (bf ? P1X1 : P1X0);
        const char* sW = (const char*)smem_all + 4 * (bf ? P1W1 : P1W0);
        const char* wp = sW + (ocw * 32 + q) * 32 + r * 8;
        uint2 Alo[2], Ahi[2];
#pragma unroll
        for (int mt = 0; mt < 2; mt++) {
            Alo[mt] = *(const uint2*)(wp + mt * 512);
            Ahi[mt] = *(const uint2*)(wp + mt * 512 + 256);
        }
#pragma unroll
        for (int nt = 0; nt < 8; nt++) {
            const char* xp = sX + (ph * 64 + nt * 8 + q) * 32 + r * 8;
            uint2 Bv = *(const uint2*)(xp);
            mma16(acc[0][nt], Alo[0].x, Ahi[0].x, Alo[0].y, Ahi[0].y, Bv.x, Bv.y);
            mma16(acc[1][nt], Alo[1].x, Ahi[1].x, Alo[1].y, Ahi[1].y, Bv.x, Bv.y);
        }
        __syncthreads();
        if (k + 2 < 8) stage(k + 2, bf);
        cp_commit();
    }

    float s1 = 0.f, s2 = 0.f;
#pragma unroll
    for (int i = 0; i < 2; i++)
#pragma unroll
        for (int j = 0; j < 8; j++)
#pragma unroll
            for (int l = 0; l < 4; l++) {
                float v = acc[i][j][l];
                s1 += v; s2 += v * v;
            }
#pragma unroll
    for (int off = 16; off > 0; off >>= 1) {
        s1 += __shfl_xor_sync(0xffffffffu, s1, off);
        s2 += __shfl_xor_sync(0xffffffffu, s2, off);
    }
    float* red = smem_all + RED1;
    if (lane == 0) { red[wid * 2] = s1; red[wid * 2 + 1] = s2; }

    float* stg = smem_all;
#pragma unroll
    for (int mt = 0; mt < 2; mt++)
#pragma unroll
        for (int nt = 0; nt < 8; nt++)
#pragma unroll
            for (int j = 0; j < 4; j++) {
                int hcl = ocw * 32 + mt * 16 + q + 8 * (j >> 1);
                int w = nt * 8 + 2 * r + (j & 1);
                stg[hcl * 132 + ph * 64 + w] = acc[mt][nt][j];
            }
    __syncthreads();
    if (tid < 2) {
        float a = red[tid * 8 + 0] + red[tid * 8 + 2] + red[tid * 8 + 4] + red[tid * 8 + 6];
        float bq = red[tid * 8 + 1] + red[tid * 8 + 3] + red[tid * 8 + 5] + red[tid * 8 + 7];
        int slot = b * 8 + ht * 2 + tid;
        g_part1[(slot * 32 + pt) * 2 + 0] = a;
        g_part1[(slot * 32 + pt) * 2 + 1] = bq;
    }
    for (int idx = tid; idx < 4096; idx += 256) {
        int hcl = idx >> 5, p4 = (idx & 31) * 4;
        float4 v = *(const float4*)(stg + hcl * 132 + p4);
        __half2* dst = (__half2*)(g_h1 + (size_t)(b * NHC + ht * 128 + hcl) * HWSZ +
                                  pt * 128 + p4);
        dst[0] = __floats2half2_rn(v.x, v.y);
        dst[1] = __floats2half2_rn(v.z, v.w);
    }
}

// ---------------- dw: compact stride-2 output, fp16 ----------------
__global__ __launch_bounds__(256) void k_dw(const float* __restrict__ w_dw,
                                            const float* __restrict__ s1v,
                                            const float* __restrict__ b1v) {
    __shared__ float sa[4356];
    __shared__ float red[512];
    int tid = threadIdx.x;
    int ch = blockIdx.x, b = blockIdx.y;
    float m  = g_ms1[(b * 8 + (ch >> 6)) * 2 + 0];
    float rs = g_ms1[(b * 8 + (ch >> 6)) * 2 + 1];
    float sc = s1v[ch], bi = b1v[ch];
    for (int idx = tid; idx < 4356; idx += 256) sa[idx] = 0.f;
    __syncthreads();
    const __half* src = g_h1 + (size_t)(b * NHC + ch) * 4096;
    for (int idx = tid; idx < 512; idx += 256) {
        int r = idx >> 3, w8 = (idx & 7) * 8;
        __align__(16) __half raw[8];
        *(uint4*)raw = *(const uint4*)(src + r * 64 + w8);
        float* d = sa + (r + 1) * 66 + 1 + w8;
#pragma unroll
        for (int j = 0; j < 8; j++)
            d[j] = silu_f((__half2float(raw[j]) - m) * rs * sc + bi);
    }
    __syncthreads();
    float wd[9];
#pragma unroll
    for (int j = 0; j < 9; j++) wd[j] = w_dw[ch * 9 + j];
    int r = tid >> 2, w0 = (tid & 3) * 16;
    float s1 = 0.f, s2 = 0.f;
    __half* orow = g_h2 + (size_t)(b * NHC + ch) * 1024 + (r >> 1) * 32;
    bool reven = (r & 1) == 0;
#pragma unroll
    for (int k = 0; k < 16; k++) {
        int w = w0 + k;
        float a = 0.f;
#pragma unroll
        for (int dr = 0; dr < 3; dr++)
#pragma unroll
            for (int dt = 0; dt < 3; dt++)
                a += sa[(r + dr) * 66 + w + dt] * wd[dr * 3 + dt];
        s1 += a; s2 += a * a;
        if (reven && !(w & 1)) orow[w >> 1] = __float2half(a);
    }
    red[tid] = s1; red[256 + tid] = s2;
    __syncthreads();
    for (int st = 128; st > 0; st >>= 1) {
        if (tid < st) { red[tid] += red[tid + st]; red[256 + tid] += red[256 + tid + st]; }
        __syncthreads();
    }
    if (tid == 0) {
        int slot = b * 8 + (ch >> 6);
        g_part2[(slot * 64 + (ch & 63)) * 2 + 0] = red[0];
        g_part2[(slot * 64 + (ch & 63)) * 2 + 1] = red[256];
    }
}

// ---------------- norm2: GN2+SiLU -> pw2 B operand (reuses g_combp) --------
__global__ void k_norm2(const float* __restrict__ s2v, const float* __restrict__ b2v) {
    int idx = blockIdx.x * 256 + threadIdx.x;   // 524288 = B*32*1024
    int px = idx & 1023, chunk = (idx >> 10) & 31, b = idx >> 15;
    __align__(16) __half o[16];
#pragma unroll
    for (int j = 0; j < 16; j++) {
        int hc = chunk * 16 + kmap(j);
        float v = __half2float(g_h2[(size_t)(b * NHC + hc) * 1024 + px]);
        float m  = g_ms2[(b * 8 + (hc >> 6)) * 2 + 0];
        float rr = g_ms2[(b * 8 + (hc >> 6)) * 2 + 1];
        o[j] = __float2half(silu_f((v - m) * rr * s2v[hc] + b2v[hc]));
    }
    uint4* dst = (uint4*)(g_combp + (size_t)idx * 16);
    dst[0] = ((uint4*)o)[0];
    dst[1] = ((uint4*)o)[1];
}

// ---------------- pw2: fp16 mma, block 128co x 64px, K=512 -----------------
__global__ __launch_bounds__(256) void k_pw2_mma() {
    __shared__ __align__(16) float sm[3072];
    int tid = threadIdx.x;
    int wid = tid >> 5, lane = tid & 31;
    int q = lane >> 2, r = lane & 3;
    int pt = blockIdx.x, b = blockIdx.y;
    unsigned smem_u = (unsigned)__cvta_generic_to_shared(sm);

    float acc[8][4];
#pragma unroll
    for (int j = 0; j < 8; j++)
#pragma unroll
        for (int l = 0; l < 4; l++) acc[j][l] = 0.f;

    auto stage = [&](int chunk, int bf) {
        unsigned sx = smem_u + 4u * (bf ? 1536 : 0);
        unsigned sw = smem_u + 4u * (bf ? 2048 : 512);
        const __half* xsrc = g_combp + ((size_t)(b * 32 + chunk) * 1024 + pt * 64) * 16;
        const __half* wsrc = g_w2r + (size_t)chunk * 2048;
        if (tid < 128) cp16(sx + tid * 16u, xsrc + tid * 8, 16);
        cp16(sw + tid * 16u, wsrc + tid * 8, 16);
    };

    stage(0, 0); cp_commit();
    stage(1, 1); cp_commit();

    for (int k = 0; k < 32; k++) {
        cp_wait1();
        __syncthreads();
        int bf = k & 1;
        const char* sX = (const char*)sm + 4 * (bf ? 1536 : 0);
        const char* sW = (const char*)sm + 4 * (bf ? 2048 : 512);
        const char* wp = sW + (wid * 16 + q) * 32 + r * 8;
        uint2 Alo = *(const uint2*)(wp);
        uint2 Ahi = *(const uint2*)(wp + 256);
#pragma unroll
        for (int nt = 0; nt < 8; nt++) {
            const char* xp = sX + (nt * 8 + q) * 32 + r * 8;
            uint2 Bv = *(const uint2*)(xp);
            mma16(acc[nt], Alo.x, Ahi.x, Alo.y, Ahi.y, Bv.x, Bv.y);
        }
        __syncthreads();
        if (k + 2 < 32) stage(k + 2, bf);
        cp_commit();
    }

    float s1 = 0.f, s2 = 0.f;
#pragma unroll
    for (int j = 0; j < 8; j++)
#pragma unroll
        for (int l = 0; l < 4; l++) {
            float v = acc[j][l];
            s1 += v; s2 += v * v;
        }
#pragma unroll
    for (int off = 16; off > 0; off >>= 1) {
        s1 += __shfl_xor_sync(0xffffffffu, s1, off);
        s2 += __shfl_xor_sync(0xffffffffu, s2, off);
    }
    if (lane == 0) {
        g_part3[((b * 8 + wid) * 16 + pt) * 2 + 0] = s1;
        g_part3[((b * 8 + wid) * 16 + pt) * 2 + 1] = s2;
    }

#pragma unroll
    for (int nt = 0; nt < 8; nt++)
#pragma unroll
        for (int l = 0; l < 4; l++) {
            int co = wid * 16 + q + 8 * (l >> 1);
            int pi = pt * 64 + nt * 8 + 2 * r + (l & 1);
            g_h3[((b * NC + co) << 10) + pi] = acc[nt][l];
        }
}

// ---------------- final ----------------
__global__ void k_out(float* __restrict__ out,
                      const float* __restrict__ s3v, const float* __restrict__ b3v) {
    int idx = blockIdx.x * 256 + threadIdx.x;
    int co = (idx >> 10) & 127, b = idx >> 17;
    int g = co >> 4;
    float m  = g_ms3[(b * 8 + g) * 2 + 0];
    float rs = g_ms3[(b * 8 + g) * 2 + 1];
    float t = (g_h3[idx] - m) * rs * s3v[co] + b3v[co];
    out[idx] = silu_f(t);
}

// ---------------- launch ----------------
extern "C" void kernel_launch(void* const* d_in, const int* in_sizes, int n_in,
                              void* d_out, int out_size) {
    const float* x      = (const float*)d_in[0];
    const float* w_exp  = (const float*)d_in[1];
    const float* gs_e   = (const float*)d_in[2];
    const float* gb_e   = (const float*)d_in[3];
    const float* w1     = (const float*)d_in[4];
    const float* b1     = (const float*)d_in[5];
    const float* w2     = (const float*)d_in[6];
    const float* b2     = (const float*)d_in[7];
    const float* w_pw1  = (const float*)d_in[8];
    const float* gn1_s  = (const float*)d_in[9];
    const float* gn1_b  = (const float*)d_in[10];
    const float* w_dw   = (const float*)d_in[11];
    const float* gn2_s  = (const float*)d_in[12];
    const float* gn2_b  = (const float*)d_in[13];
    const float* w_pw2  = (const float*)d_in[14];
    const float* gn3_s  = (const float*)d_in[15];
    const float* gn3_b  = (const float*)d_in[16];
    float* out = (float*)d_out;

    static bool attr_done = false;
    if (!attr_done) {
        cudaFuncSetAttribute(k_expert_mma, cudaFuncAttributeMaxDynamicSharedMemorySize,
                             EXPF * 4);
        cudaFuncSetAttribute(k_pw1_mma, cudaFuncAttributeMaxDynamicSharedMemorySize,
                             PW1F * 4);
        attr_done = true;
    }

    // expert at launch index 3 so ncu's fixed sample lands on it
    k_xform_x<<<2048, 256>>>(x);
    k_xform_w<<<288, 256>>>(w_exp);
    k_router<<<1, 1024>>>(w1, b1, w2, b2);
    k_expert_mma<<<dim3(16, 2, 128), 256, EXPF * 4>>>();
    k_xform_w1<<<16, 256>>>(w_pw1);
    k_xform_w2<<<16, 256>>>(w_pw2);
    k_finalize<<<4, 256>>>(0);
    k_combine<<<1024, 256>>>(x, gs_e, gb_e);
    k_pw1_mma<<<dim3(4, 32, 16), 256, PW1F * 4>>>();
    k_finalize<<<4, 256>>>(1);
    k_dw<<<dim3(512, 16), 256>>>(w_dw, gn1_s, gn1_b);
    k_finalize<<<4, 256>>>(2);
    k_norm2<<<2048, 256>>>(gn2_s, gn2_b);
    k_pw2_mma<<<dim3(16, 16), 256>>>();
    k_finalize<<<4, 256>>>(3);
    k_out<<<8192, 256>>>(out, gn3_s, gn3_b);
}

// round 15
// speedup vs baseline: 1.6872x; 1.1444x over previous
#include <cuda_runtime.h>
#include <cuda_fp16.h>
#include <math.h>

// ---------------- problem constants ----------------
#define NB   16
#define NC   128
#define NHC  512
#define HWSZ 4096

// ---------------- scratch ----------------
__device__ __half g_z[67108864];     // [E*B][C][HW] expert conv raw (fp16)
__device__ __half g_combp[8388608];  // [B][chunk8][px4096][16kp] fp16 (reused by norm2)
__device__ __half g_h1[33554432];
__device__ __half g_h2[8388608];     // COMPACT [B][HC][32][32] fp16
__device__ float  g_h3[2097152];
__device__ float  g_wts[128];
__device__ __half g_xr[8388608];     // [B][chunk8][h][w][16kp]
__device__ __half g_wr[1179648];     // [E][chunk8][tap9][oc128][16kp]
__device__ __half g_w1r[65536];      // [ht4][chunk8][hcl128][16kp]
__device__ __half g_w2r[65536];      // [chunk32][co128][16kp]
__device__ float g_part_exp[1024 * 64 * 2];
__device__ float g_ms_exp[1024 * 2];
__device__ float g_part1[128 * 32 * 2];
__device__ float g_ms1[128 * 2];
__device__ float g_part2[128 * 64 * 2];
__device__ float g_ms2[128 * 2];
__device__ float g_part3[128 * 16 * 2];
__device__ float g_ms3[128 * 2];

__device__ __forceinline__ float silu_f(float x) {
    // fast-path: MUFU.EX2 + MUFU.RCP instead of IEEE divide sequence (~2 ulp)
    return __fdividef(x, 1.0f + __expf(-x));
}
// permuted k index: j in [0,16) -> k, so thread r's 4 contiguous halves are
// k = {2r, 2r+1, 2r+8, 2r+9}
__device__ __forceinline__ int kmap(int j) {
    return ((j >> 2) * 2) + (j & 1) + ((j >> 1) & 1) * 8;
}
__device__ __forceinline__ void cp16(unsigned s, const void* g, int sz) {
    asm volatile("cp.async.cg.shared.global [%0], [%1], 16, %2;\n"
                 :: "r"(s), "l"(g), "r"(sz) : "memory");
}
__device__ __forceinline__ void cp_commit() {
    asm volatile("cp.async.commit_group;\n" ::: "memory");
}
__device__ __forceinline__ void cp_wait1() {
    asm volatile("cp.async.wait_group 1;\n" ::: "memory");
}
__device__ __forceinline__ void mma16(float* c, unsigned a0, unsigned a1, unsigned a2,
                                      unsigned a3, unsigned b0, unsigned b1) {
    asm volatile("mma.sync.aligned.m16n8k16.row.col.f32.f16.f16.f32 "
                 "{%0,%1,%2,%3}, {%4,%5,%6,%7}, {%8,%9}, {%0,%1,%2,%3};"
                 : "+f"(c[0]), "+f"(c[1]), "+f"(c[2]), "+f"(c[3])
                 : "r"(a0), "r"(a1), "r"(a2), "r"(a3), "r"(b0), "r"(b1));
}

// ---------------- transforms (fp16 + permute) ----------
__global__ void k_xform_x(const float* __restrict__ x) {
    int idx = blockIdx.x * 256 + threadIdx.x;   // 524288
    int w = idx & 63, h = (idx >> 6) & 63, chunk = (idx >> 12) & 7, b = idx >> 15;
    __align__(16) __half o[16];
#pragma unroll
    for (int j = 0; j < 16; j++) {
        int c = chunk * 16 + kmap(j);
        o[j] = __float2half(x[((b * 128 + c) << 12) + (h << 6) + w]);
    }
    uint4* dst = (uint4*)(g_xr + (size_t)idx * 16);
    dst[0] = ((uint4*)o)[0];
    dst[1] = ((uint4*)o)[1];
}

__global__ void k_xform_w(const float* __restrict__ w_exp) {
    int idx = blockIdx.x * 256 + threadIdx.x;   // 73728
    int oc = idx & 127;
    int t2 = idx >> 7;
    int tap = t2 % 9, ec = t2 / 9;
    int chunk = ec & 7, e = ec >> 3;
    __align__(16) __half o[16];
#pragma unroll
    for (int j = 0; j < 16; j++) {
        int c = chunk * 16 + kmap(j);
        o[j] = __float2half(w_exp[((e * 128 + oc) * 128 + c) * 9 + tap]);
    }
    uint4* dst = (uint4*)(g_wr + (size_t)idx * 16);
    dst[0] = ((uint4*)o)[0];
    dst[1] = ((uint4*)o)[1];
}

__global__ void k_xform_w1(const float* __restrict__ w_pw1) {
    int idx = blockIdx.x * 256 + threadIdx.x;   // 4096
    int hcl = idx & 127, chunk = (idx >> 7) & 7, ht = idx >> 10;
    __align__(16) __half o[16];
#pragma unroll
    for (int j = 0; j < 16; j++) {
        int c = chunk * 16 + kmap(j);
        o[j] = __float2half(w_pw1[(ht * 128 + hcl) * 128 + c]);
    }
    uint4* dst = (uint4*)(g_w1r + (size_t)idx * 16);
    dst[0] = ((uint4*)o)[0];
    dst[1] = ((uint4*)o)[1];
}

__global__ void k_xform_w2(const float* __restrict__ w_pw2) {
    int idx = blockIdx.x * 256 + threadIdx.x;   // 4096
    int co = idx & 127, chunk = idx >> 7;
    __align__(16) __half o[16];
#pragma unroll
    for (int j = 0; j < 16; j++) {
        int hc = chunk * 16 + kmap(j);
        o[j] = __float2half(w_pw2[co * NHC + hc]);
    }
    uint4* dst = (uint4*)(g_w2r + (size_t)idx * 16);
    dst[0] = ((uint4*)o)[0];
    dst[1] = ((uint4*)o)[1];
}

// ---------------- router ----------------
__global__ void k_router(const float* __restrict__ w1, const float* __restrict__ b1,
                         const float* __restrict__ w2, const float* __restrict__ b2) {
    __shared__ float feats[16 * 32];
    __shared__ float hid[16 * 64];
    __shared__ float lg[16 * 8];
    int tid = threadIdx.x;
    if (tid < 512) {
        int p = tid >> 5, f = tid & 31;
        int py = p >> 2, px = p & 3;
        int k = f & 7, kind = f >> 3;
        float freq = exp2f((float)k) * 3.14159265358979323846f;
        float cy = (py + 0.5f) * 0.25f;
        float cx = (px + 0.5f) * 0.25f;
        float v;
        if (kind == 0)      v = sinf(cy * freq);
        else if (kind == 1) v = cosf(cy * freq);
        else if (kind == 2) v = sinf(cx * freq);
        else                v = cosf(cx * freq);
        feats[p * 32 + f] = v;
    }
    __syncthreads();
    {
        int p = tid >> 6, hh = tid & 63;
        float a = b1[hh];
        for (int f = 0; f < 32; f++) a += feats[p * 32 + f] * w1[f * 64 + hh];
        hid[p * 64 + hh] = a / (1.0f + expf(-a));
    }
    __syncthreads();
    if (tid < 128) {
        int p = tid >> 3, e = tid & 7;
        float a = b2[e];
        for (int hh = 0; hh < 64; hh++) a += hid[p * 64 + hh] * w2[hh * 8 + e];
        lg[p * 8 + e] = a;
    }
    __syncthreads();
    if (tid < 16) {
        float mx = -1e30f;
        for (int e = 0; e < 8; e++) mx = fmaxf(mx, lg[tid * 8 + e]);
        float ex[8], s = 0.f;
        for (int e = 0; e < 8; e++) { ex[e] = expf(lg[tid * 8 + e] - mx); s += ex[e]; }
        float inv = 1.0f / s;
        for (int e = 0; e < 8; e++) g_wts[tid * 8 + e] = ex[e] * inv;
    }
}

// ---------------- expert conv: fp16 mma, block 64oc x 256px, 2 CTA/SM -------
#define XA0 0
#define XA1 3168
#define WA0 6336
#define WA1 10944
#define EXPF 15552

extern __shared__ float smem_all[];

__global__ __launch_bounds__(256, 2) void k_expert_mma() {
    int tid = threadIdx.x;
    int wid = tid >> 5, lane = tid & 31;
    int q = lane >> 2, r = lane & 3;
    int ocw = wid & 1, orow = wid >> 1;
    int hb = blockIdx.x, octile = blockIdx.y;
    int b = blockIdx.z & 15, e = blockIdx.z >> 4;
    unsigned smem_u = (unsigned)__cvta_generic_to_shared(smem_all);

    float acc[2][8][4];
#pragma unroll
    for (int i = 0; i < 2; i++)
#pragma unroll
        for (int j = 0; j < 8; j++)
#pragma unroll
            for (int l = 0; l < 4; l++) acc[i][j][l] = 0.f;

    if (tid < 192) {
        int bf = tid / 96, t = tid % 96;
        int row = t >> 4, side = (t >> 3) & 1, f = t & 7;
        smem_all[(bf ? XA1 : XA0) + row * 528 + (side ? 65 : 0) * 8 + f] = 0.f;
    }

    auto stage = [&](int chunk, int bf) {
        unsigned sx = smem_u + 4u * (bf ? XA1 : XA0);
        unsigned sw = smem_u + 4u * (bf ? WA1 : WA0);
        const __half* xs = g_xr + (size_t)(b * 8 + chunk) * 65536;
        for (int idx = tid; idx < 768; idx += 256) {
            int row = idx >> 7, f4 = idx & 127;
            int ih = 4 * hb - 1 + row;
            bool v = ((unsigned)ih < 64u);
            cp16(sx + (unsigned)(row * 2112 + 32 + f4 * 16),
                 xs + (size_t)(v ? ih : 0) * 1024 + f4 * 8, v ? 16 : 0);
        }
        const __half* ws = g_wr + (size_t)(e * 8 + chunk) * 18432 + octile * 1024;
        for (int idx = tid; idx < 1152; idx += 256) {
            int tap = idx >> 7, rem = idx & 127;
            cp16(sw + idx * 16u, ws + (size_t)tap * 2048 + rem * 8, 16);
        }
    };

    stage(0, 0); cp_commit();
    stage(1, 1); cp_commit();

    for (int c = 0; c < 8; c++) {
        cp_wait1();
        __syncthreads();
        int bf = c & 1;
        const char* sX = (const char*)smem_all + 4 * (bf ? XA1 : XA0);
        const char* sW = (const char*)smem_all + 4 * (bf ? WA1 : WA0);
#pragma unroll
        for (int tap = 0; tap < 9; tap++) {
            int dy = tap / 3, dx = tap - dy * 3;
            const char* wp = sW + tap * 2048 + (ocw * 32 + q) * 32 + r * 8;
            uint2 Alo[2], Ahi[2];
#pragma unroll
            for (int mt = 0; mt < 2; mt++) {
                Alo[mt] = *(const uint2*)(wp + mt * 512);
                Ahi[mt] = *(const uint2*)(wp + mt * 512 + 256);
            }
            const char* xp = sX + (orow + dy) * 2112 + (q + dx) * 32 + r * 8;
#pragma unroll
            for (int nt = 0; nt < 8; nt++) {
                uint2 Bv = *(const uint2*)(xp + nt * 256);
                mma16(acc[0][nt], Alo[0].x, Ahi[0].x, Alo[0].y, Ahi[0].y, Bv.x, Bv.y);
                mma16(acc[1][nt], Alo[1].x, Ahi[1].x, Alo[1].y, Ahi[1].y, Bv.x, Bv.y);
            }
        }
        __syncthreads();
        if (c + 2 < 8) stage(c + 2, bf);
        cp_commit();
    }

#pragma unroll
    for (int mt = 0; mt < 2; mt++) {
        float s1 = 0.f, s2 = 0.f;
#pragma unroll
        for (int nt = 0; nt < 8; nt++)
#pragma unroll
            for (int j = 0; j < 4; j++) {
                float v = acc[mt][nt][j];
                s1 += v; s2 += v * v;
            }
#pragma unroll
        for (int off = 16; off > 0; off >>= 1) {
            s1 += __shfl_xor_sync(0xffffffffu, s1, off);
            s2 += __shfl_xor_sync(0xffffffffu, s2, off);
        }
        if (lane == 0) {
            int g = octile * 4 + ocw * 2 + mt;
            int slot = (e * NB + b) * 8 + g;
            g_part_exp[(slot * 64 + hb * 4 + orow) * 2 + 0] = s1;
            g_part_exp[(slot * 64 + hb * 4 + orow) * 2 + 1] = s2;
        }
    }

    __half* stg = (__half*)smem_all;
#pragma unroll
    for (int mt = 0; mt < 2; mt++)
#pragma unroll
        for (int nt = 0; nt < 8; nt++) {
            int oc0 = ocw * 32 + mt * 16 + q;
            int px = orow * 64 + nt * 8 + 2 * r;
            *(__half2*)(stg + oc0 * 264 + px) =
                __floats2half2_rn(acc[mt][nt][0], acc[mt][nt][1]);
            *(__half2*)(stg + (oc0 + 8) * 264 + px) =
                __floats2half2_rn(acc[mt][nt][2], acc[mt][nt][3]);
        }
    __syncthreads();
    size_t zbase = (size_t)((e * NB + b) * NC + octile * 64) * HWSZ;
    for (int idx = tid; idx < 2048; idx += 256) {
        int oc = idx >> 5, p8 = (idx & 31) * 8;
        uint4 v = *(const uint4*)(stg + oc * 264 + p8);
        int h = 4 * hb + (p8 >> 6), w = p8 & 63;
        *(uint4*)(g_z + zbase + (size_t)oc * HWSZ + h * 64 + w) = v;
    }
}

// ---------------- finalize stats ----------------
__global__ void k_finalize(int which) {
    const float* part; float* ms; int nper, nslots; float invN;
    if (which == 0)      { part = g_part_exp; ms = g_ms_exp; nper = 64; nslots = 1024; invN = 1.0f / 65536.0f; }
    else if (which == 1) { part = g_part1;    ms = g_ms1;    nper = 32; nslots = 128;  invN = 1.0f / 262144.0f; }
    else if (which == 2) { part = g_part2;    ms = g_ms2;    nper = 64; nslots = 128;  invN = 1.0f / 262144.0f; }
    else                 { part = g_part3;    ms = g_ms3;    nper = 16; nslots = 128;  invN = 1.0f / 16384.0f; }
    int s = blockIdx.x * blockDim.x + threadIdx.x;
    if (s >= nslots) return;
    float s1 = 0.f, s2 = 0.f;
    for (int i = 0; i < nper; i++) {
        s1 += part[(s * nper + i) * 2 + 0];
        s2 += part[(s * nper + i) * 2 + 1];
    }
    float m = s1 * invN;
    float v = s2 * invN - m * m;
    ms[s * 2 + 0] = m;
    ms[s * 2 + 1] = rsqrtf(v + 1e-5f);
}

// ---------------- combine: 2 px per thread, half2 z loads ----------------
__global__ __launch_bounds__(256) void k_combine(const float* __restrict__ x,
                                                 const float* __restrict__ gs,
                                                 const float* __restrict__ gb) {
    int idx = blockIdx.x * 256 + threadIdx.x;   // 262144 = B*8*2048
    int px2 = idx & 2047, chunk = (idx >> 11) & 7, b = idx >> 14;
    int px = px2 * 2;
    int h = px >> 6, w = px & 63;
    int patch = ((h >> 4) << 2) + (w >> 4);   // same for px and px+1 (w even)
    float ra[16], rb[16];
#pragma unroll
    for (int j = 0; j < 16; j++) {
        int c = chunk * 16 + kmap(j);
        float2 xv = *(const float2*)(x + ((b * 128 + c) << 12) + px);
        ra[j] = xv.x; rb[j] = xv.y;
    }
#pragma unroll
    for (int e = 0; e < 8; e++) {
        float m  = g_ms_exp[(((e * NB + b) * 8) + chunk) * 2 + 0];
        float rs = g_ms_exp[(((e * NB + b) * 8) + chunk) * 2 + 1];
        float wt = g_wts[patch * 8 + e];
#pragma unroll
        for (int j = 0; j < 16; j++) {
            int c = chunk * 16 + kmap(j);
            __half2 zv = *(const __half2*)(g_z +
                ((size_t)((e * NB + b) * NC + c)) * HWSZ + px);
            float2 zf = __half22float2(zv);
            float gsc = gs[e * NC + c], gbc = gb[e * NC + c];
            ra[j] += wt * silu_f((zf.x - m) * rs * gsc + gbc);
            rb[j] += wt * silu_f((zf.y - m) * rs * gsc + gbc);
        }
    }
    __half2* dst = (__half2*)(g_combp + ((size_t)(b * 8 + chunk) * 4096 + px) * 16);
#pragma unroll
    for (int j = 0; j < 8; j++)
        dst[j] = __floats2half2_rn(ra[2 * j], ra[2 * j + 1]);
#pragma unroll
    for (int j = 0; j < 8; j++)
        dst[8 + j] = __floats2half2_rn(rb[2 * j], rb[2 * j + 1]);
}

// ---------------- pw1: fp16 mma, block 128hc x 128px ----------------
#define P1X0 0
#define P1W0 1024
#define P1X1 2048
#define P1W1 3072
#define RED1 16896
#define PW1F 16928

__global__ __launch_bounds__(256, 2) void k_pw1_mma() {
    int tid = threadIdx.x;
    int wid = tid >> 5, lane = tid & 31;
    int q = lane >> 2, r = lane & 3;
    int ocw = wid >> 1, ph = wid & 1;
    int ht = blockIdx.x, pt = blockIdx.y, b = blockIdx.z;
    unsigned smem_u = (unsigned)__cvta_generic_to_shared(smem_all);

    float acc[2][8][4];
#pragma unroll
    for (int i = 0; i < 2; i++)
#pragma unroll
        for (int j = 0; j < 8; j++)
#pragma unroll
            for (int l = 0; l < 4; l++) acc[i][j][l] = 0.f;

    auto stage = [&](int chunk, int bf) {
        unsigned sxa = smem_u + 4u * (bf ? P1X1 : P1X0);
        unsigned swa = smem_u + 4u * (bf ? P1W1 : P1W0);
        const __half* xsrc = g_combp + ((size_t)(b * 8 + chunk) * 4096 + pt * 128) * 16;
        const __half* wsrc = g_w1r + (ht * 8 + chunk) * 2048;
        cp16(sxa + tid * 16u, xsrc + tid * 8, 16);
        cp16(swa + tid * 16u, wsrc + tid * 8, 16);
    };

    stage(0, 0); cp_commit();
    stage(1, 1); cp_commit();

    for (int k = 0; k < 8; k++) {
        cp_wait1();
        __syncthreads();
        int bf = k & 1;
        const char* sX = (const char*)smem_all + 4 * (bf ? P1X1 : P1X0);
        const char* sW = (const char*)smem_all + 4 * (bf ? P1W1 : P1W0);
        const char* wp = sW + (ocw * 32 + q) * 32 + r * 8;
        uint2 Alo[2], Ahi[2];
#pragma unroll
        for (int mt = 0; mt < 2; mt++) {
            Alo[mt] = *(const uint2*)(wp + mt * 512);
            Ahi[mt] = *(const uint2*)(wp + mt * 512 + 256);
        }
#pragma unroll
        for (int nt = 0; nt < 8; nt++) {
            const char* xp = sX + (ph * 64 + nt * 8 + q) * 32 + r * 8;
            uint2 Bv = *(const uint2*)(xp);
            mma16(acc[0][nt], Alo[0].x, Ahi[0].x, Alo[0].y, Ahi[0].y, Bv.x, Bv.y);
            mma16(acc[1][nt], Alo[1].x, Ahi[1].x, Alo[1].y, Ahi[1].y, Bv.x, Bv.y);
        }
        __syncthreads();
        if (k + 2 < 8) stage(k + 2, bf);
        cp_commit();
    }

    float s1 = 0.f, s2 = 0.f;
#pragma unroll
    for (int i = 0; i < 2; i++)
#pragma unroll
        for (int j = 0; j < 8; j++)
#pragma unroll
            for (int l = 0; l < 4; l++) {
                float v = acc[i][j][l];
                s1 += v; s2 += v * v;
            }
#pragma unroll
    for (int off = 16; off > 0; off >>= 1) {
        s1 += __shfl_xor_sync(0xffffffffu, s1, off);
        s2 += __shfl_xor_sync(0xffffffffu, s2, off);
    }
    float* red = smem_all + RED1;
    if (lane == 0) { red[wid * 2] = s1; red[wid * 2 + 1] = s2; }

    float* stg = smem_all;
#pragma unroll
    for (int mt = 0; mt < 2; mt++)
#pragma unroll
        for (int nt = 0; nt < 8; nt++)
#pragma unroll
            for (int j = 0; j < 4; j++) {
                int hcl = ocw * 32 + mt * 16 + q + 8 * (j >> 1);
                int w = nt * 8 + 2 * r + (j & 1);
                stg[hcl * 132 + ph * 64 + w] = acc[mt][nt][j];
            }
    __syncthreads();
    if (tid < 2) {
        float a = red[tid * 8 + 0] + red[tid * 8 + 2] + red[tid * 8 + 4] + red[tid * 8 + 6];
        float bq = red[tid * 8 + 1] + red[tid * 8 + 3] + red[tid * 8 + 5] + red[tid * 8 + 7];
        int slot = b * 8 + ht * 2 + tid;
        g_part1[(slot * 32 + pt) * 2 + 0] = a;
        g_part1[(slot * 32 + pt) * 2 + 1] = bq;
    }
    for (int idx = tid; idx < 4096; idx += 256) {
        int hcl = idx >> 5, p4 = (idx & 31) * 4;
        float4 v = *(const float4*)(stg + hcl * 132 + p4);
        __half2* dst = (__half2*)(g_h1 + (size_t)(b * NHC + ht * 128 + hcl) * HWSZ +
                                  pt * 128 + p4);
        dst[0] = __floats2half2_rn(v.x, v.y);
        dst[1] = __floats2half2_rn(v.z, v.w);
    }
}

// ---------------- dw: compact stride-2 output, fp16, shuffle reduce --------
__global__ __launch_bounds__(256) void k_dw(const float* __restrict__ w_dw,
                                            const float* __restrict__ s1v,
                                            const float* __restrict__ b1v) {
    __shared__ float sa[4356];
    __shared__ float red[16];
    int tid = threadIdx.x;
    int lane = tid & 31, wid = tid >> 5;
    int ch = blockIdx.x, b = blockIdx.y;
    float m  = g_ms1[(b * 8 + (ch >> 6)) * 2 + 0];
    float rs = g_ms1[(b * 8 + (ch >> 6)) * 2 + 1];
    float sc = s1v[ch], bi = b1v[ch];
    for (int idx = tid; idx < 4356; idx += 256) sa[idx] = 0.f;
    __syncthreads();
    const __half* src = g_h1 + (size_t)(b * NHC + ch) * 4096;
    for (int idx = tid; idx < 512; idx += 256) {
        int r = idx >> 3, w8 = (idx & 7) * 8;
        __align__(16) __half raw[8];
        *(uint4*)raw = *(const uint4*)(src + r * 64 + w8);
        float* d = sa + (r + 1) * 66 + 1 + w8;
#pragma unroll
        for (int j = 0; j < 8; j++)
            d[j] = silu_f((__half2float(raw[j]) - m) * rs * sc + bi);
    }
    __syncthreads();
    float wd[9];
#pragma unroll
    for (int j = 0; j < 9; j++) wd[j] = w_dw[ch * 9 + j];
    int r = tid >> 2, w0 = (tid & 3) * 16;
    float s1 = 0.f, s2 = 0.f;
    __half* orow = g_h2 + (size_t)(b * NHC + ch) * 1024 + (r >> 1) * 32;
    bool reven = (r & 1) == 0;
#pragma unroll
    for (int k = 0; k < 16; k++) {
        int w = w0 + k;
        float a = 0.f;
#pragma unroll
        for (int dr = 0; dr < 3; dr++)
#pragma unroll
            for (int dt = 0; dt < 3; dt++)
                a += sa[(r + dr) * 66 + w + dt] * wd[dr * 3 + dt];
        s1 += a; s2 += a * a;
        if (reven && !(w & 1)) orow[w >> 1] = __float2half(a);
    }
#pragma unroll
    for (int off = 16; off > 0; off >>= 1) {
        s1 += __shfl_xor_sync(0xffffffffu, s1, off);
        s2 += __shfl_xor_sync(0xffffffffu, s2, off);
    }
    if (lane == 0) { red[wid] = s1; red[8 + wid] = s2; }
    __syncthreads();
    if (tid == 0) {
        float a = 0.f, bq = 0.f;
#pragma unroll
        for (int i = 0; i < 8; i++) { a += red[i]; bq += red[8 + i]; }
        int slot = b * 8 + (ch >> 6);
        g_part2[(slot * 64 + (ch & 63)) * 2 + 0] = a;
        g_part2[(slot * 64 + (ch & 63)) * 2 + 1] = bq;
    }
}

// ---------------- norm2: GN2+SiLU -> pw2 B operand (reuses g_combp) --------
__global__ void k_norm2(const float* __restrict__ s2v, const float* __restrict__ b2v) {
    int idx = blockIdx.x * 256 + threadIdx.x;   // 524288 = B*32*1024
    int px = idx & 1023, chunk = (idx >> 10) & 31, b = idx >> 15;
    __align__(16) __half o[16];
#pragma unroll
    for (int j = 0; j < 16; j++) {
        int hc = chunk * 16 + kmap(j);
        float v = __half2float(g_h2[(size_t)(b * NHC + hc) * 1024 + px]);
        float m  = g_ms2[(b * 8 + (hc >> 6)) * 2 + 0];
        float rr = g_ms2[(b * 8 + (hc >> 6)) * 2 + 1];
        o[j] = __float2half(silu_f((v - m) * rr * s2v[hc] + b2v[hc]));
    }
    uint4* dst = (uint4*)(g_combp + (size_t)idx * 16);
    dst[0] = ((uint4*)o)[0];
    dst[1] = ((uint4*)o)[1];
}

// ---------------- pw2: fp16 mma, block 128co x 64px, K=512 -----------------
__global__ __launch_bounds__(256) void k_pw2_mma() {
    __shared__ __align__(16) float sm[3072];
    int tid = threadIdx.x;
    int wid = tid >> 5, lane = tid & 31;
    int q = lane >> 2, r = lane & 3;
    int pt = blockIdx.x, b = blockIdx.y;
    unsigned smem_u = (unsigned)__cvta_generic_to_shared(sm);

    float acc[8][4];
#pragma unroll
    for (int j = 0; j < 8; j++)
#pragma unroll
        for (int l = 0; l < 4; l++) acc[j][l] = 0.f;

    auto stage = [&](int chunk, int bf) {
        unsigned sx = smem_u + 4u * (bf ? 1536 : 0);
        unsigned sw = smem_u + 4u * (bf ? 2048 : 512);
        const __half* xsrc = g_combp + ((size_t)(b * 32 + chunk) * 1024 + pt * 64) * 16;
        const __half* wsrc = g_w2r + (size_t)chunk * 2048;
        if (tid < 128) cp16(sx + tid * 16u, xsrc + tid * 8, 16);
        cp16(sw + tid * 16u, wsrc + tid * 8, 16);
    };

    stage(0, 0); cp_commit();
    stage(1, 1); cp_commit();

    for (int k = 0; k < 32; k++) {
        cp_wait1();
        __syncthreads();
        int bf = k & 1;
        const char* sX = (const char*)sm + 4 * (bf ? 1536 : 0);
        const char* sW = (const char*)sm + 4 * (bf ? 2048 : 512);
        const char* wp = sW + (wid * 16 + q) * 32 + r * 8;
        uint2 Alo = *(const uint2*)(wp);
        uint2 Ahi = *(const uint2*)(wp + 256);
#pragma unroll
        for (int nt = 0; nt < 8; nt++) {
            const char* xp = sX + (nt * 8 + q) * 32 + r * 8;
            uint2 Bv = *(const uint2*)(xp);
            mma16(acc[nt], Alo.x, Ahi.x, Alo.y, Ahi.y, Bv.x, Bv.y);
        }
        __syncthreads();
        if (k + 2 < 32) stage(k + 2, bf);
        cp_commit();
    }

    float s1 = 0.f, s2 = 0.f;
#pragma unroll
    for (int j = 0; j < 8; j++)
#pragma unroll
        for (int l = 0; l < 4; l++) {
            float v = acc[j][l];
            s1 += v; s2 += v * v;
        }
#pragma unroll
    for (int off = 16; off > 0; off >>= 1) {
        s1 += __shfl_xor_sync(0xffffffffu, s1, off);
        s2 += __shfl_xor_sync(0xffffffffu, s2, off);
    }
    if (lane == 0) {
        g_part3[((b * 8 + wid) * 16 + pt) * 2 + 0] = s1;
        g_part3[((b * 8 + wid) * 16 + pt) * 2 + 1] = s2;
    }

#pragma unroll
    for (int nt = 0; nt < 8; nt++)
#pragma unroll
        for (int l = 0; l < 4; l++) {
            int co = wid * 16 + q + 8 * (l >> 1);
            int pi = pt * 64 + nt * 8 + 2 * r + (l & 1);
            g_h3[((b * NC + co) << 10) + pi] = acc[nt][l];
        }
}

// ---------------- final ----------------
__global__ void k_out(float* __restrict__ out,
                      const float* __restrict__ s3v, const float* __restrict__ b3v) {
    int idx = blockIdx.x * 256 + threadIdx.x;
    int co = (idx >> 10) & 127, b = idx >> 17;
    int g = co >> 4;
    float m  = g_ms3[(b * 8 + g) * 2 + 0];
    float rs = g_ms3[(b * 8 + g) * 2 + 1];
    float t = (g_h3[idx] - m) * rs * s3v[co] + b3v[co];
    out[idx] = silu_f(t);
}

// ---------------- launch ----------------
extern "C" void kernel_launch(void* const* d_in, const int* in_sizes, int n_in,
                              void* d_out, int out_size) {
    const float* x      = (const float*)d_in[0];
    const float* w_exp  = (const float*)d_in[1];
    const float* gs_e   = (const float*)d_in[2];
    const float* gb_e   = (const float*)d_in[3];
    const float* w1     = (const float*)d_in[4];
    const float* b1     = (const float*)d_in[5];
    const float* w2     = (const float*)d_in[6];
    const float* b2     = (const float*)d_in[7];
    const float* w_pw1  = (const float*)d_in[8];
    const float* gn1_s  = (const float*)d_in[9];
    const float* gn1_b  = (const float*)d_in[10];
    const float* w_dw   = (const float*)d_in[11];
    const float* gn2_s  = (const float*)d_in[12];
    const float* gn2_b  = (const float*)d_in[13];
    const float* w_pw2  = (const float*)d_in[14];
    const float* gn3_s  = (const float*)d_in[15];
    const float* gn3_b  = (const float*)d_in[16];
    float* out = (float*)d_out;

    static bool attr_done = false;
    if (!attr_done) {
        cudaFuncSetAttribute(k_expert_mma, cudaFuncAttributeMaxDynamicSharedMemorySize,
                             EXPF * 4);
        cudaFuncSetAttribute(k_pw1_mma, cudaFuncAttributeMaxDynamicSharedMemorySize,
                             PW1F * 4);
        attr_done = true;
    }

    // expert at launch index 3 so ncu's fixed sample lands on it
    k_xform_x<<<2048, 256>>>(x);
    k_xform_w<<<288, 256>>>(w_exp);
    k_router<<<1, 1024>>>(w1, b1, w2, b2);
    k_expert_mma<<<dim3(16, 2, 128), 256, EXPF * 4>>>();
    k_xform_w1<<<16, 256>>>(w_pw1);
    k_xform_w2<<<16, 256>>>(w_pw2);
    k_finalize<<<4, 256>>>(0);
    k_combine<<<1024, 256>>>(x, gs_e, gb_e);
    k_pw1_mma<<<dim3(4, 32, 16), 256, PW1F * 4>>>();
    k_finalize<<<4, 256>>>(1);
    k_dw<<<dim3(512, 16), 256>>>(w_dw, gn1_s, gn1_b);
    k_finalize<<<4, 256>>>(2);
    k_norm2<<<2048, 256>>>(gn2_s, gn2_b);
    k_pw2_mma<<<dim3(16, 16), 256>>>();
    k_finalize<<<4, 256>>>(3);
    k_out<<<8192, 256>>>(out, gn3_s, gn3_b);
}

// round 16
// speedup vs baseline: 1.7032x; 1.0095x over previous
#include <cuda_runtime.h>
#include <cuda_fp16.h>
#include <math.h>

// ---------------- problem constants ----------------
#define NB   16
#define NC   128
#define NHC  512
#define HWSZ 4096

// ---------------- scratch ----------------
__device__ __half g_z[67108864];     // [E*B][C][HW] expert conv raw (fp16)
__device__ __half g_combp[8388608];  // [B][chunk8][px4096][16kp] fp16 (reused by norm2)
__device__ __half g_h1[33554432];
__device__ __half g_h2[8388608];     // COMPACT [B][HC][32][32] fp16
__device__ float  g_h3[2097152];
__device__ float  g_wts[128];
__device__ __half g_xr[8388608];     // [B][chunk8][h][w][16kp]
__device__ __half g_wr[1179648];     // [E][chunk8][tap9][oc128][16kp]
__device__ __half g_w1r[65536];      // [ht4][chunk8][hcl128][16kp]
__device__ __half g_w2r[65536];      // [chunk32][co128][16kp]
__device__ float g_part_exp[1024 * 64 * 2];
__device__ float g_ms_exp[1024 * 2];
__device__ float g_part1[128 * 32 * 2];
__device__ float g_ms1[128 * 2];
__device__ float g_part2[128 * 64 * 2];
__device__ float g_ms2[128 * 2];
__device__ float g_part3[128 * 16 * 2];
__device__ float g_ms3[128 * 2];

// exact-ish silu (2 MUFU) - used where counts are tiny
__device__ __forceinline__ float silu_f(float x) {
    return __fdividef(x, 1.0f + __expf(-x));
}
// 1-MUFU silu via tanh.approx: silu(x) = 0.5*x*(1+tanh(x/2))
__device__ __forceinline__ float silu_t(float x) {
    float t;
    asm("tanh.approx.f32 %0, %1;" : "=f"(t) : "f"(x * 0.5f));
    return 0.5f * x * (1.0f + t);
}
// permuted k index: j in [0,16) -> k, so thread r's 4 contiguous halves are
// k = {2r, 2r+1, 2r+8, 2r+9}
__device__ __forceinline__ int kmap(int j) {
    return ((j >> 2) * 2) + (j & 1) + ((j >> 1) & 1) * 8;
}
__device__ __forceinline__ void cp16(unsigned s, const void* g, int sz) {
    asm volatile("cp.async.cg.shared.global [%0], [%1], 16, %2;\n"
                 :: "r"(s), "l"(g), "r"(sz) : "memory");
}
__device__ __forceinline__ void cp_commit() {
    asm volatile("cp.async.commit_group;\n" ::: "memory");
}
__device__ __forceinline__ void cp_wait1() {
    asm volatile("cp.async.wait_group 1;\n" ::: "memory");
}
__device__ __forceinline__ void mma16(float* c, unsigned a0, unsigned a1, unsigned a2,
                                      unsigned a3, unsigned b0, unsigned b1) {
    asm volatile("mma.sync.aligned.m16n8k16.row.col.f32.f16.f16.f32 "
                 "{%0,%1,%2,%3}, {%4,%5,%6,%7}, {%8,%9}, {%0,%1,%2,%3};"
                 : "+f"(c[0]), "+f"(c[1]), "+f"(c[2]), "+f"(c[3])
                 : "r"(a0), "r"(a1), "r"(a2), "r"(a3), "r"(b0), "r"(b1));
}

// ---------------- merged transform: x (blocks 0..2047) + w_exp (2048..2335) --
__global__ void k_xform_xw(const float* __restrict__ x,
                           const float* __restrict__ w_exp) {
    int bid = blockIdx.x;
    if (bid < 2048) {
        int idx = bid * 256 + threadIdx.x;   // 524288
        int w = idx & 63, h = (idx >> 6) & 63, chunk = (idx >> 12) & 7, b = idx >> 15;
        __align__(16) __half o[16];
#pragma unroll
        for (int j = 0; j < 16; j++) {
            int c = chunk * 16 + kmap(j);
            o[j] = __float2half(x[((b * 128 + c) << 12) + (h << 6) + w]);
        }
        uint4* dst = (uint4*)(g_xr + (size_t)idx * 16);
        dst[0] = ((uint4*)o)[0];
        dst[1] = ((uint4*)o)[1];
    } else {
        int idx = (bid - 2048) * 256 + threadIdx.x;   // 73728
        int oc = idx & 127;
        int t2 = idx >> 7;
        int tap = t2 % 9, ec = t2 / 9;
        int chunk = ec & 7, e = ec >> 3;
        __align__(16) __half o[16];
#pragma unroll
        for (int j = 0; j < 16; j++) {
            int c = chunk * 16 + kmap(j);
            o[j] = __float2half(w_exp[((e * 128 + oc) * 128 + c) * 9 + tap]);
        }
        uint4* dst = (uint4*)(g_wr + (size_t)idx * 16);
        dst[0] = ((uint4*)o)[0];
        dst[1] = ((uint4*)o)[1];
    }
}

// ---------------- merged transform: w1 (blocks 0..15) + w2 (16..31) ---------
__global__ void k_xform_w12(const float* __restrict__ w_pw1,
                            const float* __restrict__ w_pw2) {
    int bid = blockIdx.x;
    if (bid < 16) {
        int idx = bid * 256 + threadIdx.x;   // 4096
        int hcl = idx & 127, chunk = (idx >> 7) & 7, ht = idx >> 10;
        __align__(16) __half o[16];
#pragma unroll
        for (int j = 0; j < 16; j++) {
            int c = chunk * 16 + kmap(j);
            o[j] = __float2half(w_pw1[(ht * 128 + hcl) * 128 + c]);
        }
        uint4* dst = (uint4*)(g_w1r + (size_t)idx * 16);
        dst[0] = ((uint4*)o)[0];
        dst[1] = ((uint4*)o)[1];
    } else {
        int idx = (bid - 16) * 256 + threadIdx.x;   // 4096
        int co = idx & 127, chunk = idx >> 7;
        __align__(16) __half o[16];
#pragma unroll
        for (int j = 0; j < 16; j++) {
            int hc = chunk * 16 + kmap(j);
            o[j] = __float2half(w_pw2[co * NHC + hc]);
        }
        uint4* dst = (uint4*)(g_w2r + (size_t)idx * 16);
        dst[0] = ((uint4*)o)[0];
        dst[1] = ((uint4*)o)[1];
    }
}

// ---------------- router (exact silu; count trivial) ----------------
__global__ void k_router(const float* __restrict__ w1, const float* __restrict__ b1,
                         const float* __restrict__ w2, const float* __restrict__ b2) {
    __shared__ float feats[16 * 32];
    __shared__ float hid[16 * 64];
    __shared__ float lg[16 * 8];
    int tid = threadIdx.x;
    if (tid < 512) {
        int p = tid >> 5, f = tid & 31;
        int py = p >> 2, px = p & 3;
        int k = f & 7, kind = f >> 3;
        float freq = exp2f((float)k) * 3.14159265358979323846f;
        float cy = (py + 0.5f) * 0.25f;
        float cx = (px + 0.5f) * 0.25f;
        float v;
        if (kind == 0)      v = sinf(cy * freq);
        else if (kind == 1) v = cosf(cy * freq);
        else if (kind == 2) v = sinf(cx * freq);
        else                v = cosf(cx * freq);
        feats[p * 32 + f] = v;
    }
    __syncthreads();
    {
        int p = tid >> 6, hh = tid & 63;
        float a = b1[hh];
        for (int f = 0; f < 32; f++) a += feats[p * 32 + f] * w1[f * 64 + hh];
        hid[p * 64 + hh] = a / (1.0f + expf(-a));
    }
    __syncthreads();
    if (tid < 128) {
        int p = tid >> 3, e = tid & 7;
        float a = b2[e];
        for (int hh = 0; hh < 64; hh++) a += hid[p * 64 + hh] * w2[hh * 8 + e];
        lg[p * 8 + e] = a;
    }
    __syncthreads();
    if (tid < 16) {
        float mx = -1e30f;
        for (int e = 0; e < 8; e++) mx = fmaxf(mx, lg[tid * 8 + e]);
        float ex[8], s = 0.f;
        for (int e = 0; e < 8; e++) { ex[e] = expf(lg[tid * 8 + e] - mx); s += ex[e]; }
        float inv = 1.0f / s;
        for (int e = 0; e < 8; e++) g_wts[tid * 8 + e] = ex[e] * inv;
    }
}

// ---------------- expert conv: fp16 mma, block 64oc x 256px, 2 CTA/SM -------
#define XA0 0
#define XA1 3168
#define WA0 6336
#define WA1 10944
#define EXPF 15552

extern __shared__ float smem_all[];

__global__ __launch_bounds__(256, 2) void k_expert_mma() {
    int tid = threadIdx.x;
    int wid = tid >> 5, lane = tid & 31;
    int q = lane >> 2, r = lane & 3;
    int ocw = wid & 1, orow = wid >> 1;
    int hb = blockIdx.x, octile = blockIdx.y;
    int b = blockIdx.z & 15, e = blockIdx.z >> 4;
    unsigned smem_u = (unsigned)__cvta_generic_to_shared(smem_all);

    float acc[2][8][4];
#pragma unroll
    for (int i = 0; i < 2; i++)
#pragma unroll
        for (int j = 0; j < 8; j++)
#pragma unroll
            for (int l = 0; l < 4; l++) acc[i][j][l] = 0.f;

    if (tid < 192) {
        int bf = tid / 96, t = tid % 96;
        int row = t >> 4, side = (t >> 3) & 1, f = t & 7;
        smem_all[(bf ? XA1 : XA0) + row * 528 + (side ? 65 : 0) * 8 + f] = 0.f;
    }

    auto stage = [&](int chunk, int bf) {
        unsigned sx = smem_u + 4u * (bf ? XA1 : XA0);
        unsigned sw = smem_u + 4u * (bf ? WA1 : WA0);
        const __half* xs = g_xr + (size_t)(b * 8 + chunk) * 65536;
        for (int idx = tid; idx < 768; idx += 256) {
            int row = idx >> 7, f4 = idx & 127;
            int ih = 4 * hb - 1 + row;
            bool v = ((unsigned)ih < 64u);
            cp16(sx + (unsigned)(row * 2112 + 32 + f4 * 16),
                 xs + (size_t)(v ? ih : 0) * 1024 + f4 * 8, v ? 16 : 0);
        }
        const __half* ws = g_wr + (size_t)(e * 8 + chunk) * 18432 + octile * 1024;
        for (int idx = tid; idx < 1152; idx += 256) {
            int tap = idx >> 7, rem = idx & 127;
            cp16(sw + idx * 16u, ws + (size_t)tap * 2048 + rem * 8, 16);
        }
    };

    stage(0, 0); cp_commit();
    stage(1, 1); cp_commit();

    for (int c = 0; c < 8; c++) {
        cp_wait1();
        __syncthreads();
        int bf = c & 1;
        const char* sX = (const char*)smem_all + 4 * (bf ? XA1 : XA0);
        const char* sW = (const char*)smem_all + 4 * (bf ? WA1 : WA0);
#pragma unroll
        for (int tap = 0; tap < 9; tap++) {
            int dy = tap / 3, dx = tap - dy * 3;
            const char* wp = sW + tap * 2048 + (ocw * 32 + q) * 32 + r * 8;
            uint2 Alo[2], Ahi[2];
#pragma unroll
            for (int mt = 0; mt < 2; mt++) {
                Alo[mt] = *(const uint2*)(wp + mt * 512);
                Ahi[mt] = *(const uint2*)(wp + mt * 512 + 256);
            }
            const char* xp = sX + (orow + dy) * 2112 + (q + dx) * 32 + r * 8;
#pragma unroll
            for (int nt = 0; nt < 8; nt++) {
                uint2 Bv = *(const uint2*)(xp + nt * 256);
                mma16(acc[0][nt], Alo[0].x, Ahi[0].x, Alo[0].y, Ahi[0].y, Bv.x, Bv.y);
                mma16(acc[1][nt], Alo[1].x, Ahi[1].x, Alo[1].y, Ahi[1].y, Bv.x, Bv.y);
            }
        }
        __syncthreads();
        if (c + 2 < 8) stage(c + 2, bf);
        cp_commit();
    }

#pragma unroll
    for (int mt = 0; mt < 2; mt++) {
        float s1 = 0.f, s2 = 0.f;
#pragma unroll
        for (int nt = 0; nt < 8; nt++)
#pragma unroll
            for (int j = 0; j < 4; j++) {
                float v = acc[mt][nt][j];
                s1 += v; s2 += v * v;
            }
#pragma unroll
        for (int off = 16; off > 0; off >>= 1) {
            s1 += __shfl_xor_sync(0xffffffffu, s1, off);
            s2 += __shfl_xor_sync(0xffffffffu, s2, off);
        }
        if (lane == 0) {
            int g = octile * 4 + ocw * 2 + mt;
            int slot = (e * NB + b) * 8 + g;
            g_part_exp[(slot * 64 + hb * 4 + orow) * 2 + 0] = s1;
            g_part_exp[(slot * 64 + hb * 4 + orow) * 2 + 1] = s2;
        }
    }

    __half* stg = (__half*)smem_all;
#pragma unroll
    for (int mt = 0; mt < 2; mt++)
#pragma unroll
        for (int nt = 0; nt < 8; nt++) {
            int oc0 = ocw * 32 + mt * 16 + q;
            int px = orow * 64 + nt * 8 + 2 * r;
            *(__half2*)(stg + oc0 * 264 + px) =
                __floats2half2_rn(acc[mt][nt][0], acc[mt][nt][1]);
            *(__half2*)(stg + (oc0 + 8) * 264 + px) =
                __floats2half2_rn(acc[mt][nt][2], acc[mt][nt][3]);
        }
    __syncthreads();
    size_t zbase = (size_t)((e * NB + b) * NC + octile * 64) * HWSZ;
    for (int idx = tid; idx < 2048; idx += 256) {
        int oc = idx >> 5, p8 = (idx & 31) * 8;
        uint4 v = *(const uint4*)(stg + oc * 264 + p8);
        int h = 4 * hb + (p8 >> 6), w = p8 & 63;
        *(uint4*)(g_z + zbase + (size_t)oc * HWSZ + h * 64 + w) = v;
    }
}

// ---------------- finalize stats ----------------
__global__ void k_finalize(int which) {
    const float* part; float* ms; int nper, nslots; float invN;
    if (which == 0)      { part = g_part_exp; ms = g_ms_exp; nper = 64; nslots = 1024; invN = 1.0f / 65536.0f; }
    else if (which == 1) { part = g_part1;    ms = g_ms1;    nper = 32; nslots = 128;  invN = 1.0f / 262144.0f; }
    else if (which == 2) { part = g_part2;    ms = g_ms2;    nper = 64; nslots = 128;  invN = 1.0f / 262144.0f; }
    else                 { part = g_part3;    ms = g_ms3;    nper = 16; nslots = 128;  invN = 1.0f / 16384.0f; }
    int s = blockIdx.x * blockDim.x + threadIdx.x;
    if (s >= nslots) return;
    float s1 = 0.f, s2 = 0.f;
    for (int i = 0; i < nper; i++) {
        s1 += part[(s * nper + i) * 2 + 0];
        s2 += part[(s * nper + i) * 2 + 1];
    }
    float m = s1 * invN;
    float v = s2 * invN - m * m;
    ms[s * 2 + 0] = m;
    ms[s * 2 + 1] = rsqrtf(v + 1e-5f);
}

// ---------------- combine: 2 px per thread, half2 z loads, tanh silu -------
__global__ __launch_bounds__(256) void k_combine(const float* __restrict__ x,
                                                 const float* __restrict__ gs,
                                                 const float* __restrict__ gb) {
    int idx = blockIdx.x * 256 + threadIdx.x;   // 262144 = B*8*2048
    int px2 = idx & 2047, chunk = (idx >> 11) & 7, b = idx >> 14;
    int px = px2 * 2;
    int h = px >> 6, w = px & 63;
    int patch = ((h >> 4) << 2) + (w >> 4);
    float ra[16], rb[16];
#pragma unroll
    for (int j = 0; j < 16; j++) {
        int c = chunk * 16 + kmap(j);
        float2 xv = *(const float2*)(x + ((b * 128 + c) << 12) + px);
        ra[j] = xv.x; rb[j] = xv.y;
    }
#pragma unroll
    for (int e = 0; e < 8; e++) {
        float m  = g_ms_exp[(((e * NB + b) * 8) + chunk) * 2 + 0];
        float rs = g_ms_exp[(((e * NB + b) * 8) + chunk) * 2 + 1];
        float wt = g_wts[patch * 8 + e];
#pragma unroll
        for (int j = 0; j < 16; j++) {
            int c = chunk * 16 + kmap(j);
            __half2 zv = *(const __half2*)(g_z +
                ((size_t)((e * NB + b) * NC + c)) * HWSZ + px);
            float2 zf = __half22float2(zv);
            float gsc = gs[e * NC + c], gbc = gb[e * NC + c];
            ra[j] += wt * silu_t((zf.x - m) * rs * gsc + gbc);
            rb[j] += wt * silu_t((zf.y - m) * rs * gsc + gbc);
        }
    }
    __half2* dst = (__half2*)(g_combp + ((size_t)(b * 8 + chunk) * 4096 + px) * 16);
#pragma unroll
    for (int j = 0; j < 8; j++)
        dst[j] = __floats2half2_rn(ra[2 * j], ra[2 * j + 1]);
#pragma unroll
    for (int j = 0; j < 8; j++)
        dst[8 + j] = __floats2half2_rn(rb[2 * j], rb[2 * j + 1]);
}

// ---------------- pw1: fp16 mma, block 128hc x 128px ----------------
#define P1X0 0
#define P1W0 1024
#define P1X1 2048
#define P1W1 3072
#define RED1 16896
#define PW1F 16928

__global__ __launch_bounds__(256, 2) void k_pw1_mma() {
    int tid = threadIdx.x;
    int wid = tid >> 5, lane = tid & 31;
    int q = lane >> 2, r = lane & 3;
    int ocw = wid >> 1, ph = wid & 1;
    int ht = blockIdx.x, pt = blockIdx.y, b = blockIdx.z;
    unsigned smem_u = (unsigned)__cvta_generic_to_shared(smem_all);

    float acc[2][8][4];
#pragma unroll
    for (int i = 0; i < 2; i++)
#pragma unroll
        for (int j = 0; j < 8; j++)
#pragma unroll
            for (int l = 0; l < 4; l++) acc[i][j][l] = 0.f;

    auto stage = [&](int chunk, int bf) {
        unsigned sxa = smem_u + 4u * (bf ? P1X1 : P1X0);
        unsigned swa = smem_u + 4u * (bf ? P1W1 : P1W0);
        const __half* xsrc = g_combp + ((size_t)(b * 8 + chunk) * 4096 + pt * 128) * 16;
        const __half* wsrc = g_w1r + (ht * 8 + chunk) * 2048;
        cp16(sxa + tid * 16u, xsrc + tid * 8, 16);
        cp16(swa + tid * 16u, wsrc + tid * 8, 16);
    };

    stage(0, 0); cp_commit();
    stage(1, 1); cp_commit();

    for (int k = 0; k < 8; k++) {
        cp_wait1();
        __syncthreads();
        int bf = k & 1;
        const char* sX = (const char*)smem_all + 4 * (bf ? P1X1 : P1X0);
        const char* sW = (const char*)smem_all + 4 * (bf ? P1W1 : P1W0);
        const char* wp = sW + (ocw * 32 + q) * 32 + r * 8;
        uint2 Alo[2], Ahi[2];
#pragma unroll
        for (int mt = 0; mt < 2; mt++) {
            Alo[mt] = *(const uint2*)(wp + mt * 512);
            Ahi[mt] = *(const uint2*)(wp + mt * 512 + 256);
        }
#pragma unroll
        for (int nt = 0; nt < 8; nt++) {
            const char* xp = sX + (ph * 64 + nt * 8 + q) * 32 + r * 8;
            uint2 Bv = *(const uint2*)(xp);
            mma16(acc[0][nt], Alo[0].x, Ahi[0].x, Alo[0].y, Ahi[0].y, Bv.x, Bv.y);
            mma16(acc[1][nt], Alo[1].x, Ahi[1].x, Alo[1].y, Ahi[1].y, Bv.x, Bv.y);
        }
        __syncthreads();
        if (k + 2 < 8) stage(k + 2, bf);
        cp_commit();
    }

    float s1 = 0.f, s2 = 0.f;
#pragma unroll
    for (int i = 0; i < 2; i++)
#pragma unroll
        for (int j = 0; j < 8; j++)
#pragma unroll
            for (int l = 0; l < 4; l++) {
                float v = acc[i][j][l];
                s1 += v; s2 += v * v;
            }
#pragma unroll
    for (int off = 16; off > 0; off >>= 1) {
        s1 += __shfl_xor_sync(0xffffffffu, s1, off);
        s2 += __shfl_xor_sync(0xffffffffu, s2, off);
    }
    float* red = smem_all + RED1;
    if (lane == 0) { red[wid * 2] = s1; red[wid * 2 + 1] = s2; }

    float* stg = smem_all;
#pragma unroll
    for (int mt = 0; mt < 2; mt++)
#pragma unroll
        for (int nt = 0; nt < 8; nt++)
#pragma unroll
            for (int j = 0; j < 4; j++) {
                int hcl = ocw * 32 + mt * 16 + q + 8 * (j >> 1);
                int w = nt * 8 + 2 * r + (j & 1);
                stg[hcl * 132 + ph * 64 + w] = acc[mt][nt][j];
            }
    __syncthreads();
    if (tid < 2) {
        float a = red[tid * 8 + 0] + red[tid * 8 + 2] + red[tid * 8 + 4] + red[tid * 8 + 6];
        float bq = red[tid * 8 + 1] + red[tid * 8 + 3] + red[tid * 8 + 5] + red[tid * 8 + 7];
        int slot = b * 8 + ht * 2 + tid;
        g_part1[(slot * 32 + pt) * 2 + 0] = a;
        g_part1[(slot * 32 + pt) * 2 + 1] = bq;
    }
    for (int idx = tid; idx < 4096; idx += 256) {
        int hcl = idx >> 5, p4 = (idx & 31) * 4;
        float4 v = *(const float4*)(stg + hcl * 132 + p4);
        __half2* dst = (__half2*)(g_h1 + (size_t)(b * NHC + ht * 128 + hcl) * HWSZ +
                                  pt * 128 + p4);
        dst[0] = __floats2half2_rn(v.x, v.y);
        dst[1] = __floats2half2_rn(v.z, v.w);
    }
}

// ---------------- dw: compact stride-2 output, fp16, shuffle reduce --------
__global__ __launch_bounds__(256) void k_dw(const float* __restrict__ w_dw,
                                            const float* __restrict__ s1v,
                                            const float* __restrict__ b1v) {
    __shared__ float sa[4356];
    __shared__ float red[16];
    int tid = threadIdx.x;
    int lane = tid & 31, wid = tid >> 5;
    int ch = blockIdx.x, b = blockIdx.y;
    float m  = g_ms1[(b * 8 + (ch >> 6)) * 2 + 0];
    float rs = g_ms1[(b * 8 + (ch >> 6)) * 2 + 1];
    float sc = s1v[ch], bi = b1v[ch];
    for (int idx = tid; idx < 4356; idx += 256) sa[idx] = 0.f;
    __syncthreads();
    const __half* src = g_h1 + (size_t)(b * NHC + ch) * 4096;
    for (int idx = tid; idx < 512; idx += 256) {
        int r = idx >> 3, w8 = (idx & 7) * 8;
        __align__(16) __half raw[8];
        *(uint4*)raw = *(const uint4*)(src + r * 64 + w8);
        float* d = sa + (r + 1) * 66 + 1 + w8;
#pragma unroll
        for (int j = 0; j < 8; j++)
            d[j] = silu_t((__half2float(raw[j]) - m) * rs * sc + bi);
    }
    __syncthreads();
    float wd[9];
#pragma unroll
    for (int j = 0; j < 9; j++) wd[j] = w_dw[ch * 9 + j];
    int r = tid >> 2, w0 = (tid & 3) * 16;
    float s1 = 0.f, s2 = 0.f;
    __half* orow = g_h2 + (size_t)(b * NHC + ch) * 1024 + (r >> 1) * 32;
    bool reven = (r & 1) == 0;
#pragma unroll
    for (int k = 0; k < 16; k++) {
        int w = w0 + k;
        float a = 0.f;
#pragma unroll
        for (int dr = 0; dr < 3; dr++)
#pragma unroll
            for (int dt = 0; dt < 3; dt++)
                a += sa[(r + dr) * 66 + w + dt] * wd[dr * 3 + dt];
        s1 += a; s2 += a * a;
        if (reven && !(w & 1)) orow[w >> 1] = __float2half(a);
    }
#pragma unroll
    for (int off = 16; off > 0; off >>= 1) {
        s1 += __shfl_xor_sync(0xffffffffu, s1, off);
        s2 += __shfl_xor_sync(0xffffffffu, s2, off);
    }
    if (lane == 0) { red[wid] = s1; red[8 + wid] = s2; }
    __syncthreads();
    if (tid == 0) {
        float a = 0.f, bq = 0.f;
#pragma unroll
        for (int i = 0; i < 8; i++) { a += red[i]; bq += red[8 + i]; }
        int slot = b * 8 + (ch >> 6);
        g_part2[(slot * 64 + (ch & 63)) * 2 + 0] = a;
        g_part2[(slot * 64 + (ch & 63)) * 2 + 1] = bq;
    }
}

// ---------------- norm2: GN2+SiLU -> pw2 B operand (reuses g_combp) --------
__global__ void k_norm2(const float* __restrict__ s2v, const float* __restrict__ b2v) {
    int idx = blockIdx.x * 256 + threadIdx.x;   // 524288 = B*32*1024
    int px = idx & 1023, chunk = (idx >> 10) & 31, b = idx >> 15;
    __align__(16) __half o[16];
#pragma unroll
    for (int j = 0; j < 16; j++) {
        int hc = chunk * 16 + kmap(j);
        float v = __half2float(g_h2[(size_t)(b * NHC + hc) * 1024 + px]);
        float m  = g_ms2[(b * 8 + (hc >> 6)) * 2 + 0];
        float rr = g_ms2[(b * 8 + (hc >> 6)) * 2 + 1];
        o[j] = __float2half(silu_t((v - m) * rr * s2v[hc] + b2v[hc]));
    }
    uint4* dst = (uint4*)(g_combp + (size_t)idx * 16);
    dst[0] = ((uint4*)o)[0];
    dst[1] = ((uint4*)o)[1];
}

// ---------------- pw2: fp16 mma, block 128co x 64px, K=512 -----------------
__global__ __launch_bounds__(256) void k_pw2_mma() {
    __shared__ __align__(16) float sm[3072];
    int tid = threadIdx.x;
    int wid = tid >> 5, lane = tid & 31;
    int q = lane >> 2, r = lane & 3;
    int pt = blockIdx.x, b = blockIdx.y;
    unsigned smem_u = (unsigned)__cvta_generic_to_shared(sm);

    float acc[8][4];
#pragma unroll
    for (int j = 0; j < 8; j++)
#pragma unroll
        for (int l = 0; l < 4; l++) acc[j][l] = 0.f;

    auto stage = [&](int chunk, int bf) {
        unsigned sx = smem_u + 4u * (bf ? 1536 : 0);
        unsigned sw = smem_u + 4u * (bf ? 2048 : 512);
        const __half* xsrc = g_combp + ((size_t)(b * 32 + chunk) * 1024 + pt * 64) * 16;
        const __half* wsrc = g_w2r + (size_t)chunk * 2048;
        if (tid < 128) cp16(sx + tid * 16u, xsrc + tid * 8, 16);
        cp16(sw + tid * 16u, wsrc + tid * 8, 16);
    };

    stage(0, 0); cp_commit();
    stage(1, 1); cp_commit();

    for (int k = 0; k < 32; k++) {
        cp_wait1();
        __syncthreads();
        int bf = k & 1;
        const char* sX = (const char*)sm + 4 * (bf ? 1536 : 0);
        const char* sW = (const char*)sm + 4 * (bf ? 2048 : 512);
        const char* wp = sW + (wid * 16 + q) * 32 + r * 8;
        uint2 Alo = *(const uint2*)(wp);
        uint2 Ahi = *(const uint2*)(wp + 256);
#pragma unroll
        for (int nt = 0; nt < 8; nt++) {
            const char* xp = sX + (nt * 8 + q) * 32 + r * 8;
            uint2 Bv = *(const uint2*)(xp);
            mma16(acc[nt], Alo.x, Ahi.x, Alo.y, Ahi.y, Bv.x, Bv.y);
        }
        __syncthreads();
        if (k + 2 < 32) stage(k + 2, bf);
        cp_commit();
    }

    float s1 = 0.f, s2 = 0.f;
#pragma unroll
    for (int j = 0; j < 8; j++)
#pragma unroll
        for (int l = 0; l < 4; l++) {
            float v = acc[j][l];
            s1 += v; s2 += v * v;
        }
#pragma unroll
    for (int off = 16; off > 0; off >>= 1) {
        s1 += __shfl_xor_sync(0xffffffffu, s1, off);
        s2 += __shfl_xor_sync(0xffffffffu, s2, off);
    }
    if (lane == 0) {
        g_part3[((b * 8 + wid) * 16 + pt) * 2 + 0] = s1;
        g_part3[((b * 8 + wid) * 16 + pt) * 2 + 1] = s2;
    }

#pragma unroll
    for (int nt = 0; nt < 8; nt++)
#pragma unroll
        for (int l = 0; l < 4; l++) {
            int co = wid * 16 + q + 8 * (l >> 1);
            int pi = pt * 64 + nt * 8 + 2 * r + (l & 1);
            g_h3[((b * NC + co) << 10) + pi] = acc[nt][l];
        }
}

// ---------------- final ----------------
__global__ void k_out(float* __restrict__ out,
                      const float* __restrict__ s3v, const float* __restrict__ b3v) {
    int idx = blockIdx.x * 256 + threadIdx.x;
    int co = (idx >> 10) & 127, b = idx >> 17;
    int g = co >> 4;
    float m  = g_ms3[(b * 8 + g) * 2 + 0];
    float rs = g_ms3[(b * 8 + g) * 2 + 1];
    float t = (g_h3[idx] - m) * rs * s3v[co] + b3v[co];
    out[idx] = silu_t(t);
}

// ---------------- launch ----------------
extern "C" void kernel_launch(void* const* d_in, const int* in_sizes, int n_in,
                              void* d_out, int out_size) {
    const float* x      = (const float*)d_in[0];
    const float* w_exp  = (const float*)d_in[1];
    const float* gs_e   = (const float*)d_in[2];
    const float* gb_e   = (const float*)d_in[3];
    const float* w1     = (const float*)d_in[4];
    const float* b1     = (const float*)d_in[5];
    const float* w2     = (const float*)d_in[6];
    const float* b2     = (const float*)d_in[7];
    const float* w_pw1  = (const float*)d_in[8];
    const float* gn1_s  = (const float*)d_in[9];
    const float* gn1_b  = (const float*)d_in[10];
    const float* w_dw   = (const float*)d_in[11];
    const float* gn2_s  = (const float*)d_in[12];
    const float* gn2_b  = (const float*)d_in[13];
    const float* w_pw2  = (const float*)d_in[14];
    const float* gn3_s  = (const float*)d_in[15];
    const float* gn3_b  = (const float*)d_in[16];
    float* out = (float*)d_out;

    static bool attr_done = false;
    if (!attr_done) {
        cudaFuncSetAttribute(k_expert_mma, cudaFuncAttributeMaxDynamicSharedMemorySize,
                             EXPF * 4);
        cudaFuncSetAttribute(k_pw1_mma, cudaFuncAttributeMaxDynamicSharedMemorySize,
                             PW1F * 4);
        attr_done = true;
    }

    // expert at launch index 3 so ncu's fixed sample lands on it
    k_xform_xw<<<2336, 256>>>(x, w_exp);
    k_xform_w12<<<32, 256>>>(w_pw1, w_pw2);
    k_router<<<1, 1024>>>(w1, b1, w2, b2);
    k_expert_mma<<<dim3(16, 2, 128), 256, EXPF * 4>>>();
    k_finalize<<<4, 256>>>(0);
    k_combine<<<1024, 256>>>(x, gs_e, gb_e);
    k_pw1_mma<<<dim3(4, 32, 16), 256, PW1F * 4>>>();
    k_finalize<<<4, 256>>>(1);
    k_dw<<<dim3(512, 16), 256>>>(w_dw, gn1_s, gn1_b);
    k_finalize<<<4, 256>>>(2);
    k_norm2<<<2048, 256>>>(gn2_s, gn2_b);
    k_pw2_mma<<<dim3(16, 16), 256>>>();
    k_finalize<<<4, 256>>>(3);
    k_out<<<8192, 256>>>(out, gn3_s, gn3_b);
}